// round 5
// baseline (speedup 1.0000x reference)
#include <cuda_runtime.h>
#include <cuda_fp16.h>
#include <cstdint>
#include <cstddef>

// ---------------- problem constants ----------------
#define TSTEPS 256
#define BB 128      // batch
#define HH 512      // GRU hidden
#define LL 1024     // LSTM hidden
#define VV 1024     // vocab

// ---------------- config ----------------
#define NTH 256
#define BM 128
#define PBK2 128                    // k per tile (8 x k16)
#define ASTRH2 (PBK2 + 8)           // 136 halfs
#define WSTRH_G (HH + 8)            // 520 halfs
#define WSTRH_L (LL + 8)            // 1032 halfs

// smem layout offsets (halfs)
#define G_ATILE (96 * WSTRH_G)                       // 49920 (after WsG[32]+WsX[64])
#define L_ATILE (64 * WSTRH_L)                       // 66048 (after WsL[64])
#define F_ATILE (2 * 64 * ASTRH2)                    // 17408 (after Bs double buf)
#define SMEM_FUSED ((L_ATILE + 2 * BM * ASTRH2) * 2) // 201728 bytes

// ---------------- persistent device scratch ----------------
__device__ __align__(256) __half g_Wgh  [2048 * 512];   // GRU combined W (t>=2), gate-interleaved
__device__ __align__(256) __half g_Wg1h [2048 * 512];   // GRU step-1 W (x=0 path)
__device__ __align__(256) float  g_bg   [2048];         // GRU combined bias
__device__ __align__(256) __half g_Wihlh[4096 * 512];   // LSTM Wih fp16, gate-interleaved
__device__ __align__(256) float  g_bl   [4096];         // LSTM bih+bhh, interleaved
__device__ __align__(256) __half g_Whhlh[4096 * 1024];  // LSTM Whh fp16, gate-interleaved
__device__ __align__(256) __half g_fcWh [1024 * 1024];  // fc weights fp16
__device__ __align__(256) float  g_x    [2 * BB * HH];  // GRU state fp32 ping-pong
__device__ __align__(256) __half g_xh   [2 * BB * HH];  // GRU state fp16 (operand)
__device__ __align__(256) __half g_zh   [BB * HH];      // half(z)
__device__ __align__(256) __half g_seqh [TSTEPS * BB * HH];          // relu(x_t) fp16
__device__ __align__(256) float  g_Xg   [(size_t)TSTEPS * BB * 4096];// LSTM input gates (+bias)
__device__ __align__(256) __half g_hh   [2 * BB * LL];  // LSTM h fp16 ping-pong
__device__ __align__(256) float  g_c    [BB * LL];      // LSTM c fp32
__device__ __align__(256) __half g_hsh  [(size_t)TSTEPS * BB * LL];  // LSTM outputs [T,B,L]
__device__ unsigned g_bar_gru;
__device__ unsigned g_bar_xg;
__device__ unsigned g_bar_lstm;
__device__ unsigned g_fc_cnt;

// ---------------- helpers ----------------
__device__ __forceinline__ void mma_f16(float4& d,
                                        uint32_t a0, uint32_t a1, uint32_t a2, uint32_t a3,
                                        uint32_t b0, uint32_t b1) {
    asm volatile(
        "mma.sync.aligned.m16n8k16.row.col.f32.f16.f16.f32 "
        "{%0,%1,%2,%3}, {%4,%5,%6,%7}, {%8,%9}, {%0,%1,%2,%3};\n"
        : "+f"(d.x), "+f"(d.y), "+f"(d.z), "+f"(d.w)
        : "r"(a0), "r"(a1), "r"(a2), "r"(a3), "r"(b0), "r"(b1));
}

__device__ __forceinline__ float sigf(float x) { return 1.0f / (1.0f + expf(-x)); }

__device__ __forceinline__ void bar_arrive(unsigned* bar) {
    __syncthreads();
    if (threadIdx.x == 0) { __threadfence(); atomicAdd(bar, 1u); }
}
__device__ __forceinline__ void wait_ge(unsigned* bar, unsigned target) {
    if (threadIdx.x == 0) {
        unsigned v;
        do {
            asm volatile("ld.acquire.gpu.b32 %0, [%1];" : "=r"(v) : "l"(bar));
        } while (v < target);
    }
    __syncthreads();
}

// A-tile [128][PBK2] loaders: thread -> row = tid>>1, col chunks (tid&1)*8 + j*16
__device__ __forceinline__ void a_load(const __half* __restrict__ A, int ldK, int k0,
                                       int tid, uint4* pr) {
    const int row = tid >> 1, cb = (tid & 1) * 8;
#pragma unroll
    for (int j = 0; j < 8; j++)
        pr[j] = *(const uint4*)(A + (size_t)row * ldK + k0 + cb + j * 16);
}
__device__ __forceinline__ void a_store(__half* buf, int tid, const uint4* pr) {
    const int row = tid >> 1, cb = (tid & 1) * 8;
#pragma unroll
    for (int j = 0; j < 8; j++)
        *(uint4*)(buf + row * ASTRH2 + cb + j * 16) = pr[j];
}

// one PBK2 k-slab of mma: A tile in smem, B rows (weights) at stride wstr, offset kg0
template <int NI>
__device__ __forceinline__ void do_kk8(const __half* __restrict__ Ac,
                                       const __half* __restrict__ Bbase,
                                       int wstr, int kg0,
                                       int lane, int wm, int wn,
                                       float4 (&acc)[2][NI]) {
#pragma unroll
    for (int kk = 0; kk < 8; kk++) {
        const int kb = kk * 16 + 2 * (lane & 3);
        uint32_t af[2][4];
#pragma unroll
        for (int mi = 0; mi < 2; mi++) {
            const __half* ap = Ac + (wm * 32 + mi * 16 + (lane >> 2)) * ASTRH2 + kb;
            af[mi][0] = *(const uint32_t*)(ap);
            af[mi][1] = *(const uint32_t*)(ap + 8 * ASTRH2);
            af[mi][2] = *(const uint32_t*)(ap + 8);
            af[mi][3] = *(const uint32_t*)(ap + 8 * ASTRH2 + 8);
        }
#pragma unroll
        for (int ni = 0; ni < NI; ni++) {
            const __half* wp = Bbase + (size_t)(wn * (NI * 8) + ni * 8 + (lane >> 2)) * wstr + kg0 + kb;
            const uint32_t b0 = *(const uint32_t*)(wp);
            const uint32_t b1 = *(const uint32_t*)(wp + 8);
#pragma unroll
            for (int mi = 0; mi < 2; mi++)
                mma_f16(acc[mi][ni], af[mi][0], af[mi][1], af[mi][2], af[mi][3], b0, b1);
        }
    }
}

// ============================================================================
// FC work-steal: logits tile [128 x 64] = hs_t @ fcW^T + fcb, K=1024 streamed
// ============================================================================
__device__ void fc_worker(__half* smh, const float* __restrict__ fcb,
                          float* __restrict__ out) {
    __shared__ int s_tile;
    __half* Bs = smh;               // [2][64][ASTRH2]
    __half* As = smh + F_ATILE;     // [2][128][ASTRH2]

    const int tid  = threadIdx.x;
    const int lane = tid & 31;
    const int wid  = tid >> 5;
    const int wm   = wid & 3;
    const int wn   = wid >> 2;

    while (true) {
        __syncthreads();
        if (tid == 0) s_tile = (int)atomicAdd(&g_fc_cnt, 1u);
        __syncthreads();
        const int tile = s_tile;
        if (tile >= TSTEPS * 16) return;
        const int t  = tile >> 4;
        const int n0 = (tile & 15) * 64;
        wait_ge(&g_bar_lstm, 64u * (unsigned)(t + 1));

        const __half* Abh = g_hsh  + (size_t)t * BB * LL;
        const __half* Wb  = g_fcWh + (size_t)n0 * LL;

        float4 acc[2][4];
#pragma unroll
        for (int mi = 0; mi < 2; mi++)
#pragma unroll
            for (int ni = 0; ni < 4; ni++) acc[mi][ni] = make_float4(0.f, 0.f, 0.f, 0.f);

        uint4 pr[8], qr[4];
        a_load(Abh, LL, 0, tid, pr);
        {
            const int r = tid >> 2, cb = (tid & 3) * 8;
#pragma unroll
            for (int j = 0; j < 4; j++)
                qr[j] = *(const uint4*)(Wb + (size_t)r * LL + cb + j * 32);
        }
        a_store(As, tid, pr);
        {
            const int r = tid >> 2, cb = (tid & 3) * 8;
#pragma unroll
            for (int j = 0; j < 4; j++)
                *(uint4*)(Bs + r * ASTRH2 + cb + j * 32) = qr[j];
        }
        __syncthreads();

        for (int kt = 0; kt < 8; ++kt) {
            const int  cur  = kt & 1;
            const bool more = (kt + 1 < 8);
            if (more) {
                const int k0 = (kt + 1) * PBK2;
                a_load(Abh, LL, k0, tid, pr);
                const int r = tid >> 2, cb = (tid & 3) * 8;
#pragma unroll
                for (int j = 0; j < 4; j++)
                    qr[j] = *(const uint4*)(Wb + (size_t)r * LL + k0 + cb + j * 32);
            }
            do_kk8<4>(As + cur * BM * ASTRH2, Bs + cur * 64 * ASTRH2,
                      ASTRH2, 0, lane, wm, wn, acc);
            if (more) {
                const int nxt = cur ^ 1;
                a_store(As + nxt * BM * ASTRH2, tid, pr);
                const int r = tid >> 2, cb = (tid & 3) * 8;
#pragma unroll
                for (int j = 0; j < 4; j++)
                    *(uint4*)(Bs + nxt * 64 * ASTRH2 + r * ASTRH2 + cb + j * 32) = qr[j];
            }
            __syncthreads();
        }

#pragma unroll
        for (int mi = 0; mi < 2; mi++) {
#pragma unroll
            for (int ni = 0; ni < 4; ni++) {
                const int r   = wm * 32 + mi * 16 + (lane >> 2);
                const int col = n0 + wn * 32 + ni * 8 + 2 * (lane & 3);
                const float b0 = fcb[col], b1 = fcb[col + 1];
                float* o0 = out + ((size_t)r * TSTEPS + t) * VV + col;
                float* o1 = out + ((size_t)(r + 8) * TSTEPS + t) * VV + col;
                *(float2*)o0 = make_float2(acc[mi][ni].x + b0, acc[mi][ni].y + b1);
                *(float2*)o1 = make_float2(acc[mi][ni].z + b0, acc[mi][ni].w + b1);
            }
        }
    }
}

// ============================================================================
// Fused persistent kernel, grid = 148:
//   CTAs 0-63:    GRU chain (32 cols) + XG (64 cols) per step, then FC steal
//   CTAs 64-127:  LSTM chain (64 cols) gated on XG barrier, then FC steal
//   CTAs 128-147: FC work-steal from start
// ============================================================================
__global__ void __launch_bounds__(NTH)
fused_persist(const float* __restrict__ z, const float* __restrict__ fcb,
              float* __restrict__ out) {
    extern __shared__ __half smh[];
    const int tid  = threadIdx.x;
    const int lane = tid & 31;
    const int wid  = tid >> 5;
    const int wm   = wid & 3;
    const int wn   = wid >> 2;
    const int bid  = blockIdx.x;

    if (bid < 64) {
        // ================= G: GRU chain + XG =================
        __half* WsG = smh;                     // [32][WSTRH_G]
        __half* WsX = smh + 32 * WSTRH_G;      // [64][WSTRH_G]
        __half* As  = smh + G_ATILE;           // [2][128][ASTRH2]
        float*  Cs  = (float*)As;              // staging after mainloop (stride 36)
        const int n0g = bid * 32;              // GRU cols
        const int n0x = bid * 64;              // XG cols

        for (int i = tid; i < 32 * 64; i += NTH) {
            const int r = i >> 6, c = (i & 63) * 8;
            *(uint4*)(WsG + r * WSTRH_G + c) = *(const uint4*)(g_Wg1h + (size_t)(n0g + r) * HH + c);
        }
        for (int i = tid; i < 64 * 64; i += NTH) {
            const int r = i >> 6, c = (i & 63) * 8;
            *(uint4*)(WsX + r * WSTRH_G + c) = *(const uint4*)(g_Wihlh + (size_t)(n0x + r) * HH + c);
        }
        __syncthreads();

        for (int t = 1; t < TSTEPS; ++t) {
            // ---- GRU step t ----
            const __half* Abh  = (t == 1) ? g_zh : g_xh + (size_t)((t - 1) & 1) * BB * HH;
            const float*  hp32 = (t == 1) ? z    : g_x  + (size_t)((t - 1) & 1) * BB * HH;
            float*  xo32 = g_x   + (size_t)(t & 1) * BB * HH;
            __half* xoh  = g_xh  + (size_t)(t & 1) * BB * HH;
            __half* so   = g_seqh + (size_t)t * BB * HH;

            float hp[4];
#pragma unroll
            for (int s = 0; s < 4; s++) {
                const int it = tid + s * NTH;
                hp[s] = hp32[(size_t)(it >> 3) * HH + (n0g >> 2) + (it & 7)];
            }

            float4 acc[2][2];
#pragma unroll
            for (int mi = 0; mi < 2; mi++)
#pragma unroll
                for (int ni = 0; ni < 2; ni++) acc[mi][ni] = make_float4(0.f, 0.f, 0.f, 0.f);

            uint4 pr[8];
            a_load(Abh, HH, 0, tid, pr);
            a_store(As, tid, pr);
            __syncthreads();
            for (int kt = 0; kt < 4; ++kt) {
                const int  cur  = kt & 1;
                const bool more = (kt + 1 < 4);
                if (more) a_load(Abh, HH, (kt + 1) * PBK2, tid, pr);
                do_kk8<2>(As + cur * BM * ASTRH2, WsG, WSTRH_G, kt * PBK2, lane, wm, wn, acc);
                if (more) a_store(As + ((kt + 1) & 1) * BM * ASTRH2, tid, pr);
                __syncthreads();
            }

#pragma unroll
            for (int mi = 0; mi < 2; mi++) {
#pragma unroll
                for (int ni = 0; ni < 2; ni++) {
                    const int r = wm * 32 + mi * 16 + (lane >> 2);
                    const int c = wn * 16 + ni * 8 + 2 * (lane & 3);
                    const float b0 = g_bg[n0g + c], b1 = g_bg[n0g + c + 1];
                    Cs[r * 36 + c]           = acc[mi][ni].x + b0;
                    Cs[r * 36 + c + 1]       = acc[mi][ni].y + b1;
                    Cs[(r + 8) * 36 + c]     = acc[mi][ni].z + b0;
                    Cs[(r + 8) * 36 + c + 1] = acc[mi][ni].w + b1;
                }
            }
            __syncthreads();

#pragma unroll
            for (int s = 0; s < 4; s++) {
                const int it  = tid + s * NTH;
                const int u   = it & 7;
                const int row = it >> 3;
                const int jg  = (n0g >> 2) + u;
                const float4 cv = *(const float4*)(Cs + row * 36 + 4 * u);
                const float rg = sigf(cv.x);
                const float zg = sigf(cv.y);
                const float nn = tanhf(cv.z + rg * cv.w);
                const float xn = (1.f - zg) * nn + zg * hp[s];
                const int oi = row * HH + jg;
                xo32[oi] = xn;
                xoh[oi]  = __float2half_rn(xn);
                so[oi]   = __float2half_rn(fmaxf(xn, 0.f));
            }

            bar_arrive(&g_bar_gru);
            wait_ge(&g_bar_gru, 64u * (unsigned)t);   // all seq[t] ready

            // ---- XG step t: Xg[t] = seq[t] @ Wih^T + bl ----
            {
                const __half* Axh = g_seqh + (size_t)t * BB * HH;
                float4 xacc[2][4];
#pragma unroll
                for (int mi = 0; mi < 2; mi++)
#pragma unroll
                    for (int ni = 0; ni < 4; ni++) xacc[mi][ni] = make_float4(0.f, 0.f, 0.f, 0.f);

                a_load(Axh, HH, 0, tid, pr);
                a_store(As, tid, pr);
                __syncthreads();
                for (int kt = 0; kt < 4; ++kt) {
                    const int  cur  = kt & 1;
                    const bool more = (kt + 1 < 4);
                    if (more) a_load(Axh, HH, (kt + 1) * PBK2, tid, pr);
                    do_kk8<4>(As + cur * BM * ASTRH2, WsX, WSTRH_G, kt * PBK2, lane, wm, wn, xacc);
                    if (more) a_store(As + ((kt + 1) & 1) * BM * ASTRH2, tid, pr);
                    __syncthreads();
                }

#pragma unroll
                for (int mi = 0; mi < 2; mi++) {
#pragma unroll
                    for (int ni = 0; ni < 4; ni++) {
                        const int r   = wm * 32 + mi * 16 + (lane >> 2);
                        const int col = n0x + wn * 32 + ni * 8 + 2 * (lane & 3);
                        const float b0 = g_bl[col], b1 = g_bl[col + 1];
                        float* o0 = g_Xg + ((size_t)t * BB + r) * 4096 + col;
                        float* o1 = g_Xg + ((size_t)t * BB + r + 8) * 4096 + col;
                        *(float2*)o0 = make_float2(xacc[mi][ni].x + b0, xacc[mi][ni].y + b1);
                        *(float2*)o1 = make_float2(xacc[mi][ni].z + b0, xacc[mi][ni].w + b1);
                    }
                }
            }
            bar_arrive(&g_bar_xg);

            if (t == 1) {   // swap to combined weights for steps >= 2
                for (int i = tid; i < 32 * 64; i += NTH) {
                    const int r = i >> 6, c = (i & 63) * 8;
                    *(uint4*)(WsG + r * WSTRH_G + c) = *(const uint4*)(g_Wgh + (size_t)(n0g + r) * HH + c);
                }
                __syncthreads();
            }
        }
        fc_worker(smh, fcb, out);

    } else if (bid < 128) {
        // ================= L: LSTM chain =================
        __half* WsL = smh;                     // [64][WSTRH_L]
        __half* As  = smh + L_ATILE;           // [2][128][ASTRH2]
        float*  Cs  = (float*)As;              // staging (stride 68)
        const int n0 = (bid - 64) * 64;

        for (int i = tid; i < 64 * 128; i += NTH) {
            const int r = i >> 7, c = (i & 127) * 8;
            *(uint4*)(WsL + r * WSTRH_L + c) = *(const uint4*)(g_Whhlh + (size_t)(n0 + r) * LL + c);
        }
        __syncthreads();

        for (int t = 0; t < TSTEPS; ++t) {
            if (t >= 1) {
                wait_ge(&g_bar_xg,   64u * (unsigned)t);        // Xg[t] ready
                wait_ge(&g_bar_lstm, 64u * (unsigned)t);        // h[t-1] ready
            }
            const __half* Abh = g_hh + (size_t)(t & 1) * BB * LL;
            __half* hoh       = g_hh + (size_t)((t + 1) & 1) * BB * LL;

            float4 acc[2][4];
#pragma unroll
            for (int mi = 0; mi < 2; mi++)
#pragma unroll
                for (int ni = 0; ni < 4; ni++) acc[mi][ni] = make_float4(0.f, 0.f, 0.f, 0.f);

            if (t >= 1) {   // t == 0: h = 0 -> matmul contributes nothing
                uint4 pr[8];
                a_load(Abh, LL, 0, tid, pr);
                a_store(As, tid, pr);
                __syncthreads();
                for (int kt = 0; kt < 8; ++kt) {
                    const int  cur  = kt & 1;
                    const bool more = (kt + 1 < 8);
                    if (more) a_load(Abh, LL, (kt + 1) * PBK2, tid, pr);
                    do_kk8<4>(As + cur * BM * ASTRH2, WsL, WSTRH_L, kt * PBK2, lane, wm, wn, acc);
                    if (more) a_store(As + ((kt + 1) & 1) * BM * ASTRH2, tid, pr);
                    __syncthreads();
                }
            }

#pragma unroll
            for (int mi = 0; mi < 2; mi++) {
#pragma unroll
                for (int ni = 0; ni < 4; ni++) {
                    const int r = wm * 32 + mi * 16 + (lane >> 2);
                    const int c = wn * 32 + ni * 8 + 2 * (lane & 3);
                    Cs[r * 68 + c]           = acc[mi][ni].x;
                    Cs[r * 68 + c + 1]       = acc[mi][ni].y;
                    Cs[(r + 8) * 68 + c]     = acc[mi][ni].z;
                    Cs[(r + 8) * 68 + c + 1] = acc[mi][ni].w;
                }
            }
            __syncthreads();

#pragma unroll
            for (int s = 0; s < 8; s++) {
                const int it  = tid + s * NTH;
                const int u   = it & 15;
                const int row = it >> 4;
                const int jg  = (n0 >> 2) + u;
                const float4 cv = *(const float4*)(Cs + row * 68 + 4 * u);
                const float4 xg = *(const float4*)(g_Xg + ((size_t)t * BB + row) * 4096 + n0 + 4 * u);
                const float ig = sigf(cv.x + xg.x);
                const float fg = sigf(cv.y + xg.y);
                const float gg = tanhf(cv.z + xg.z);
                const float og = sigf(cv.w + xg.w);
                const int ci = row * LL + jg;
                const float cn = fg * g_c[ci] + ig * gg;
                g_c[ci] = cn;
                const float hn = og * tanhf(cn);
                hoh[ci] = __float2half_rn(hn);
                g_hsh[((size_t)t * BB + row) * LL + jg] = __float2half_rn(hn);
            }

            bar_arrive(&g_bar_lstm);
        }
        fc_worker(smh, fcb, out);

    } else {
        // ================= F: FC steal from the start =================
        fc_worker(smh, fcb, out);
    }
}

// ---------------- prep kernels ----------------
__global__ void prep_gru(const float* __restrict__ Wih, const float* __restrict__ Whh,
                         const float* __restrict__ bih, const float* __restrict__ bhh) {
    const int idx = blockIdx.x * blockDim.x + threadIdx.x;
    if (idx < 2048 * 512) {
        const int row = idx >> 9, k = idx & 511;
        const int j = row >> 2, g = row & 3;
        float wg, w1;
        if (g == 0)      { wg = Wih[j * 512 + k] + Whh[j * 512 + k];                 w1 = Whh[j * 512 + k]; }
        else if (g == 1) { wg = Wih[(512 + j) * 512 + k] + Whh[(512 + j) * 512 + k]; w1 = Whh[(512 + j) * 512 + k]; }
        else if (g == 2) { wg = Wih[(1024 + j) * 512 + k];                           w1 = 0.f; }
        else             { wg = Whh[(1024 + j) * 512 + k];                           w1 = wg; }
        g_Wgh[idx]  = __float2half_rn(wg);
        g_Wg1h[idx] = __float2half_rn(w1);
    }
    if (idx < 2048) {
        const int j = idx >> 2, g = idx & 3;
        float b;
        if (g == 0)      b = bih[j] + bhh[j];
        else if (g == 1) b = bih[512 + j] + bhh[512 + j];
        else if (g == 2) b = bih[1024 + j];
        else             b = bhh[1024 + j];
        g_bg[idx] = b;
    }
}

__global__ void prep_lstm(const float* __restrict__ Wih, const float* __restrict__ Whh,
                          const float* __restrict__ bih, const float* __restrict__ bhh,
                          const float* __restrict__ fcW) {
    const int idx = blockIdx.x * blockDim.x + threadIdx.x;
    if (idx < 4096 * 1024) {
        const int row = idx >> 10, k = idx & 1023;
        const int j = row >> 2, p = row & 3;
        g_Whhlh[idx] = __float2half_rn(Whh[(size_t)(p * 1024 + j) * 1024 + k]);
    }
    if (idx < 4096 * 512) {
        const int row = idx >> 9, k = idx & 511;
        const int j = row >> 2, p = row & 3;
        g_Wihlh[idx] = __float2half_rn(Wih[(size_t)(p * 1024 + j) * 512 + k]);
    }
    if (idx < 1024 * 1024) {
        g_fcWh[idx] = __float2half_rn(fcW[idx]);
    }
    if (idx < 4096) {
        const int j = idx >> 2, p = idx & 3;
        g_bl[idx] = bih[p * 1024 + j] + bhh[p * 1024 + j];
    }
}

// also fills Xg[0] = bl (seq[0] == 0)
__global__ void prep_zero(const float* __restrict__ z) {
    const int idx = blockIdx.x * blockDim.x + threadIdx.x;
    if (idx < BB * LL) { g_hh[idx] = __float2half_rn(0.f); g_c[idx] = 0.f; }
    if (idx < BB * HH) { g_zh[idx] = __float2half_rn(z[idx]); }
    if (idx < BB * 4096) { g_Xg[idx] = g_bl[idx & 4095]; }
    if (idx == 0) { g_bar_gru = 0u; g_bar_xg = 0u; g_bar_lstm = 0u; g_fc_cnt = 0u; }
}

// ---------------- host launcher ----------------
extern "C" void kernel_launch(void* const* d_in, const int* in_sizes, int n_in,
                              void* d_out, int out_size) {
    const float* z    = (const float*)d_in[0];
    const float* gWih = (const float*)d_in[2];
    const float* gWhh = (const float*)d_in[3];
    const float* gbih = (const float*)d_in[4];
    const float* gbhh = (const float*)d_in[5];
    const float* lWih = (const float*)d_in[6];
    const float* lWhh = (const float*)d_in[7];
    const float* lbih = (const float*)d_in[8];
    const float* lbhh = (const float*)d_in[9];
    const float* fcW  = (const float*)d_in[10];
    const float* fcb  = (const float*)d_in[11];
    float* out = (float*)d_out;

    cudaFuncSetAttribute(fused_persist, cudaFuncAttributeMaxDynamicSharedMemorySize, SMEM_FUSED);

    prep_gru <<<(2048 * 512 + 255) / 256, 256>>>(gWih, gWhh, gbih, gbhh);
    prep_lstm<<<(4096 * 1024 + 255) / 256, 256>>>(lWih, lWhh, lbih, lbhh, fcW);
    prep_zero<<<(BB * 4096 + 255) / 256, 256>>>(z);

    // single fused persistent kernel: GRU+XG | LSTM | FC pipelined across 148 SMs
    fused_persist<<<148, NTH, SMEM_FUSED>>>(z, fcb, out);
}

// round 6
// speedup vs baseline: 1.0570x; 1.0570x over previous
#include <cuda_runtime.h>
#include <cuda_fp16.h>
#include <cstdint>
#include <cstddef>

// ---------------- problem constants ----------------
#define TSTEPS 256
#define BB 128      // batch
#define HH 512      // GRU hidden
#define LL 1024     // LSTM hidden
#define VV 1024     // vocab

// ---------------- config ----------------
#define NTH 256
#define BM 128
#define PBK2 128                    // k per slab (8 x k16)
#define ASTRH2 (PBK2 + 8)           // 136 halfs
#define WSTRH_G (HH + 8)            // 520 halfs
#define WSTRH_L (LL + 8)            // 1032 halfs

#define SMEM_A_KERN ((64 * WSTRH_G + 2 * BM * ASTRH2) * 2)   // 136192 (XG side max)
#define SMEM_B_KERN ((32 * WSTRH_L + 2 * BM * ASTRH2) * 2)   // 135680
#define F_ATILE (2 * 64 * ASTRH2)   // FC: As offset after B double-buf (halfs)

// ---------------- persistent device scratch ----------------
__device__ __align__(256) __half g_Wgh  [2048 * 512];   // GRU combined W (t>=2), gate-interleaved
__device__ __align__(256) __half g_Wg1h [2048 * 512];   // GRU step-1 W (x=0 path)
__device__ __align__(256) float  g_bg   [2048];         // GRU combined bias
__device__ __align__(256) __half g_Wihlh[4096 * 512];   // LSTM Wih fp16, gate-interleaved
__device__ __align__(256) float  g_bl   [4096];         // LSTM bih+bhh, interleaved
__device__ __align__(256) __half g_Whhlh[4096 * 1024];  // LSTM Whh fp16, gate-interleaved
__device__ __align__(256) __half g_fcWh [1024 * 1024];  // fc weights fp16
__device__ __align__(256) float  g_x    [2 * BB * HH];  // GRU state fp32 ping-pong
__device__ __align__(256) __half g_xh   [2 * BB * HH];  // GRU state fp16 (operand)
__device__ __align__(256) __half g_zh   [BB * HH];      // half(z)
__device__ __align__(256) __half g_seqh [TSTEPS * BB * HH];          // relu(x_t) fp16
__device__ __align__(256) float  g_Xg   [(size_t)TSTEPS * BB * 4096];// LSTM input gates (+bias)
__device__ __align__(256) __half g_hh   [2 * BB * LL];  // LSTM h fp16 ping-pong
__device__ __align__(256) float  g_c    [BB * LL];      // LSTM c fp32
__device__ __align__(256) __half g_hsh  [(size_t)TSTEPS * BB * LL];  // LSTM outputs [T,B,L]
// barrier counters on separate 128B lines
__device__ __align__(128) unsigned g_bar_gru[32];
__device__ __align__(128) unsigned g_bar_lstm[32];
__device__ __align__(128) unsigned g_fc_cnt[32];

// ---------------- helpers ----------------
__device__ __forceinline__ void mma_f16(float4& d,
                                        uint32_t a0, uint32_t a1, uint32_t a2, uint32_t a3,
                                        uint32_t b0, uint32_t b1) {
    asm volatile(
        "mma.sync.aligned.m16n8k16.row.col.f32.f16.f16.f32 "
        "{%0,%1,%2,%3}, {%4,%5,%6,%7}, {%8,%9}, {%0,%1,%2,%3};\n"
        : "+f"(d.x), "+f"(d.y), "+f"(d.z), "+f"(d.w)
        : "r"(a0), "r"(a1), "r"(a2), "r"(a3), "r"(b0), "r"(b1));
}

__device__ __forceinline__ float sigf(float x) { return 1.0f / (1.0f + expf(-x)); }

// arrive: release-add, no full membar, no return
__device__ __forceinline__ void bar_arrive(unsigned* bar) {
    __syncthreads();
    if (threadIdx.x == 0)
        asm volatile("red.release.gpu.global.add.u32 [%0], 1;" :: "l"(bar) : "memory");
}
// wait with nanosleep backoff (keeps the barrier line quiet)
__device__ __forceinline__ void wait_ge(unsigned* bar, unsigned target) {
    if (threadIdx.x == 0) {
        unsigned v;
        asm volatile("ld.acquire.gpu.global.b32 %0, [%1];" : "=r"(v) : "l"(bar));
        while (v < target) {
            __nanosleep(64);
            asm volatile("ld.acquire.gpu.global.b32 %0, [%1];" : "=r"(v) : "l"(bar));
        }
    }
    __syncthreads();
}

// A-tile [128][PBK2] loaders: thread -> row = tid>>1, col chunks (tid&1)*8 + j*16
__device__ __forceinline__ void a_load(const __half* __restrict__ A, int ldK, int k0,
                                       int tid, uint4* pr) {
    const int row = tid >> 1, cb = (tid & 1) * 8;
#pragma unroll
    for (int j = 0; j < 8; j++)
        pr[j] = *(const uint4*)(A + (size_t)row * ldK + k0 + cb + j * 16);
}
__device__ __forceinline__ void a_store(__half* buf, int tid, const uint4* pr) {
    const int row = tid >> 1, cb = (tid & 1) * 8;
#pragma unroll
    for (int j = 0; j < 8; j++)
        *(uint4*)(buf + row * ASTRH2 + cb + j * 16) = pr[j];
}

// one PBK2 k-slab of mma: A tile in smem, B rows (weights) at stride wstr, offset kg0
template <int NI>
__device__ __forceinline__ void do_kk8(const __half* __restrict__ Ac,
                                       const __half* __restrict__ Bbase,
                                       int wstr, int kg0,
                                       int lane, int wm, int wn,
                                       float4 (&acc)[2][NI]) {
#pragma unroll
    for (int kk = 0; kk < 8; kk++) {
        const int kb = kk * 16 + 2 * (lane & 3);
        uint32_t af[2][4];
#pragma unroll
        for (int mi = 0; mi < 2; mi++) {
            const __half* ap = Ac + (wm * 32 + mi * 16 + (lane >> 2)) * ASTRH2 + kb;
            af[mi][0] = *(const uint32_t*)(ap);
            af[mi][1] = *(const uint32_t*)(ap + 8 * ASTRH2);
            af[mi][2] = *(const uint32_t*)(ap + 8);
            af[mi][3] = *(const uint32_t*)(ap + 8 * ASTRH2 + 8);
        }
#pragma unroll
        for (int ni = 0; ni < NI; ni++) {
            const __half* wp = Bbase + (size_t)(wn * (NI * 8) + ni * 8 + (lane >> 2)) * wstr + kg0 + kb;
            const uint32_t b0 = *(const uint32_t*)(wp);
            const uint32_t b1 = *(const uint32_t*)(wp + 8);
#pragma unroll
            for (int mi = 0; mi < 2; mi++)
                mma_f16(acc[mi][ni], af[mi][0], af[mi][1], af[mi][2], af[mi][3], b0, b1);
        }
    }
}

// ============================================================================
// Kernel A, grid 128: CTAs 0-63 GRU chain (32 cols); CTAs 64-127 XG (64 cols)
// ============================================================================
__global__ void __launch_bounds__(NTH)
gruxg_persist(const float* __restrict__ z) {
    extern __shared__ __half smh[];
    const int tid  = threadIdx.x;
    const int lane = tid & 31;
    const int wid  = tid >> 5;
    const int wm   = wid & 3;
    const int wn   = wid >> 2;

    if (blockIdx.x < 64) {
        // ---------------- GRU chain ----------------
        __half* Ws = smh;                     // [32][WSTRH_G]
        __half* As = smh + 32 * WSTRH_G;      // [2][128][ASTRH2]
        float*  Cs = (float*)As;              // staging (stride 36) after mainloop
        const int n0 = blockIdx.x * 32;

        for (int i = tid; i < 32 * 64; i += NTH) {
            const int r = i >> 6, c = (i & 63) * 8;
            *(uint4*)(Ws + r * WSTRH_G + c) = *(const uint4*)(g_Wg1h + (size_t)(n0 + r) * HH + c);
        }
        __syncthreads();

        for (int t = 1; t < TSTEPS; ++t) {
            const __half* Abh  = (t == 1) ? g_zh : g_xh + (size_t)((t - 1) & 1) * BB * HH;
            const float*  hp32 = (t == 1) ? z    : g_x  + (size_t)((t - 1) & 1) * BB * HH;
            float*  xo32 = g_x    + (size_t)(t & 1) * BB * HH;
            __half* xoh  = g_xh   + (size_t)(t & 1) * BB * HH;
            __half* so   = g_seqh + (size_t)t * BB * HH;

            float hp[4];
#pragma unroll
            for (int s = 0; s < 4; s++) {
                const int it = tid + s * NTH;
                hp[s] = hp32[(size_t)(it >> 3) * HH + (n0 >> 2) + (it & 7)];
            }

            float4 acc[2][2];
#pragma unroll
            for (int mi = 0; mi < 2; mi++)
#pragma unroll
                for (int ni = 0; ni < 2; ni++) acc[mi][ni] = make_float4(0.f, 0.f, 0.f, 0.f);

            uint4 pr[8];
            a_load(Abh, HH, 0, tid, pr);
            a_store(As, tid, pr);
            __syncthreads();
            for (int kt = 0; kt < 4; ++kt) {
                const int  cur  = kt & 1;
                const bool more = (kt + 1 < 4);
                if (more) a_load(Abh, HH, (kt + 1) * PBK2, tid, pr);
                do_kk8<2>(As + cur * BM * ASTRH2, Ws, WSTRH_G, kt * PBK2, lane, wm, wn, acc);
                if (more) a_store(As + ((kt + 1) & 1) * BM * ASTRH2, tid, pr);
                __syncthreads();
            }

#pragma unroll
            for (int mi = 0; mi < 2; mi++) {
#pragma unroll
                for (int ni = 0; ni < 2; ni++) {
                    const int r = wm * 32 + mi * 16 + (lane >> 2);
                    const int c = wn * 16 + ni * 8 + 2 * (lane & 3);
                    const float b0 = g_bg[n0 + c], b1 = g_bg[n0 + c + 1];
                    Cs[r * 36 + c]           = acc[mi][ni].x + b0;
                    Cs[r * 36 + c + 1]       = acc[mi][ni].y + b1;
                    Cs[(r + 8) * 36 + c]     = acc[mi][ni].z + b0;
                    Cs[(r + 8) * 36 + c + 1] = acc[mi][ni].w + b1;
                }
            }
            __syncthreads();

#pragma unroll
            for (int s = 0; s < 4; s++) {
                const int it  = tid + s * NTH;
                const int u   = it & 7;
                const int row = it >> 3;
                const int jg  = (n0 >> 2) + u;
                const float4 cv = *(const float4*)(Cs + row * 36 + 4 * u);
                const float rg = sigf(cv.x);
                const float zg = sigf(cv.y);
                const float nn = tanhf(cv.z + rg * cv.w);
                const float xn = (1.f - zg) * nn + zg * hp[s];
                const int oi = row * HH + jg;
                xo32[oi] = xn;
                xoh[oi]  = __float2half_rn(xn);
                so[oi]   = __float2half_rn(fmaxf(xn, 0.f));
            }

            bar_arrive(g_bar_gru);
            if (t < TSTEPS - 1) {
                wait_ge(g_bar_gru, 64u * (unsigned)t);
                if (t == 1) {   // swap to combined weights
                    for (int i = tid; i < 32 * 64; i += NTH) {
                        const int r = i >> 6, c = (i & 63) * 8;
                        *(uint4*)(Ws + r * WSTRH_G + c) =
                            *(const uint4*)(g_Wgh + (size_t)(n0 + r) * HH + c);
                    }
                    __syncthreads();
                }
            }
        }
    } else {
        // ---------------- XG: Xg[t] = seq[t] @ Wih^T + bl (64 cols, t = 1..255) ----------------
        __half* Ws = smh;                     // [64][WSTRH_G]
        __half* As = smh + 64 * WSTRH_G;      // [2][128][ASTRH2]
        const int n0 = (blockIdx.x - 64) * 64;

        for (int i = tid; i < 64 * 64; i += NTH) {
            const int r = i >> 6, c = (i & 63) * 8;
            *(uint4*)(Ws + r * WSTRH_G + c) = *(const uint4*)(g_Wihlh + (size_t)(n0 + r) * HH + c);
        }
        __syncthreads();

        for (int t = 1; t < TSTEPS; ++t) {
            wait_ge(g_bar_gru, 64u * (unsigned)t);
            const __half* Abh = g_seqh + (size_t)t * BB * HH;

            float4 acc[2][4];
#pragma unroll
            for (int mi = 0; mi < 2; mi++)
#pragma unroll
                for (int ni = 0; ni < 4; ni++) acc[mi][ni] = make_float4(0.f, 0.f, 0.f, 0.f);

            uint4 pr[8];
            a_load(Abh, HH, 0, tid, pr);
            a_store(As, tid, pr);
            __syncthreads();
            for (int kt = 0; kt < 4; ++kt) {
                const int  cur  = kt & 1;
                const bool more = (kt + 1 < 4);
                if (more) a_load(Abh, HH, (kt + 1) * PBK2, tid, pr);
                do_kk8<4>(As + cur * BM * ASTRH2, Ws, WSTRH_G, kt * PBK2, lane, wm, wn, acc);
                if (more) a_store(As + ((kt + 1) & 1) * BM * ASTRH2, tid, pr);
                __syncthreads();
            }

#pragma unroll
            for (int mi = 0; mi < 2; mi++) {
#pragma unroll
                for (int ni = 0; ni < 4; ni++) {
                    const int r   = wm * 32 + mi * 16 + (lane >> 2);
                    const int col = n0 + wn * 32 + ni * 8 + 2 * (lane & 3);
                    const float b0 = g_bl[col], b1 = g_bl[col + 1];
                    float* o0 = g_Xg + ((size_t)t * BB + r) * 4096 + col;
                    float* o1 = g_Xg + ((size_t)t * BB + r + 8) * 4096 + col;
                    *(float2*)o0 = make_float2(acc[mi][ni].x + b0, acc[mi][ni].y + b1);
                    *(float2*)o1 = make_float2(acc[mi][ni].z + b0, acc[mi][ni].w + b1);
                }
            }
            __syncthreads();
        }
    }
}

// ============================================================================
// FC work-steal: logits tile [128 x 64] = hs_t @ fcW^T + fcb, K=1024 streamed
// ============================================================================
__device__ void fc_worker(__half* smh, const float* __restrict__ fcb,
                          float* __restrict__ out) {
    __shared__ int s_tile;
    __half* Bs = smh;               // [2][64][ASTRH2]
    __half* As = smh + F_ATILE;     // [2][128][ASTRH2]

    const int tid  = threadIdx.x;
    const int lane = tid & 31;
    const int wid  = tid >> 5;
    const int wm   = wid & 3;
    const int wn   = wid >> 2;

    while (true) {
        __syncthreads();
        if (tid == 0) s_tile = (int)atomicAdd(&g_fc_cnt[0], 1u);
        __syncthreads();
        const int tile = s_tile;
        if (tile >= TSTEPS * 16) return;
        const int t  = tile >> 4;
        const int n0 = (tile & 15) * 64;
        wait_ge(g_bar_lstm, 128u * (unsigned)(t + 1));

        const __half* Abh = g_hsh  + (size_t)t * BB * LL;
        const __half* Wb  = g_fcWh + (size_t)n0 * LL;

        float4 acc[2][4];
#pragma unroll
        for (int mi = 0; mi < 2; mi++)
#pragma unroll
            for (int ni = 0; ni < 4; ni++) acc[mi][ni] = make_float4(0.f, 0.f, 0.f, 0.f);

        uint4 pr[8], qr[4];
        a_load(Abh, LL, 0, tid, pr);
        {
            const int r = tid >> 2, cb = (tid & 3) * 8;
#pragma unroll
            for (int j = 0; j < 4; j++)
                qr[j] = *(const uint4*)(Wb + (size_t)r * LL + cb + j * 32);
        }
        a_store(As, tid, pr);
        {
            const int r = tid >> 2, cb = (tid & 3) * 8;
#pragma unroll
            for (int j = 0; j < 4; j++)
                *(uint4*)(Bs + r * ASTRH2 + cb + j * 32) = qr[j];
        }
        __syncthreads();

        for (int kt = 0; kt < 8; ++kt) {
            const int  cur  = kt & 1;
            const bool more = (kt + 1 < 8);
            if (more) {
                const int k0 = (kt + 1) * PBK2;
                a_load(Abh, LL, k0, tid, pr);
                const int r = tid >> 2, cb = (tid & 3) * 8;
#pragma unroll
                for (int j = 0; j < 4; j++)
                    qr[j] = *(const uint4*)(Wb + (size_t)r * LL + k0 + cb + j * 32);
            }
            do_kk8<4>(As + cur * BM * ASTRH2, Bs + cur * 64 * ASTRH2,
                      ASTRH2, 0, lane, wm, wn, acc);
            if (more) {
                const int nxt = cur ^ 1;
                a_store(As + nxt * BM * ASTRH2, tid, pr);
                const int r = tid >> 2, cb = (tid & 3) * 8;
#pragma unroll
                for (int j = 0; j < 4; j++)
                    *(uint4*)(Bs + nxt * 64 * ASTRH2 + r * ASTRH2 + cb + j * 32) = qr[j];
            }
            __syncthreads();
        }

#pragma unroll
        for (int mi = 0; mi < 2; mi++) {
#pragma unroll
            for (int ni = 0; ni < 4; ni++) {
                const int r   = wm * 32 + mi * 16 + (lane >> 2);
                const int col = n0 + wn * 32 + ni * 8 + 2 * (lane & 3);
                const float b0 = fcb[col], b1 = fcb[col + 1];
                float* o0 = out + ((size_t)r * TSTEPS + t) * VV + col;
                float* o1 = out + ((size_t)(r + 8) * TSTEPS + t) * VV + col;
                *(float2*)o0 = make_float2(acc[mi][ni].x + b0, acc[mi][ni].y + b1);
                *(float2*)o1 = make_float2(acc[mi][ni].z + b0, acc[mi][ni].w + b1);
            }
        }
    }
}

// ============================================================================
// Kernel B, grid 148: CTAs 0-127 LSTM chain (32 cols) then FC; 128-147 FC
// ============================================================================
__global__ void __launch_bounds__(NTH)
lstmfc_persist(const float* __restrict__ fcb, float* __restrict__ out) {
    extern __shared__ __half smh[];
    const int tid  = threadIdx.x;
    const int lane = tid & 31;
    const int wid  = tid >> 5;
    const int wm   = wid & 3;
    const int wn   = wid >> 2;

    if (blockIdx.x < 128) {
        __half* Ws = smh;                     // [32][WSTRH_L]
        __half* As = smh + 32 * WSTRH_L;      // [2][128][ASTRH2]
        float*  Cs = (float*)As;              // staging (stride 36)
        const int n0 = blockIdx.x * 32;

        for (int i = tid; i < 32 * 128; i += NTH) {
            const int r = i >> 7, c = (i & 127) * 8;
            *(uint4*)(Ws + r * WSTRH_L + c) = *(const uint4*)(g_Whhlh + (size_t)(n0 + r) * LL + c);
        }
        __syncthreads();

        for (int t = 0; t < TSTEPS; ++t) {
            const __half* Abh = g_hh + (size_t)(t & 1) * BB * LL;
            __half* hoh       = g_hh + (size_t)((t + 1) & 1) * BB * LL;

            float4 xg[4];
            float  cc[4];
#pragma unroll
            for (int s = 0; s < 4; s++) {
                const int it  = tid + s * NTH;
                const int row = it >> 3;
                const int u   = it & 7;
                xg[s] = *(const float4*)(g_Xg + ((size_t)t * BB + row) * 4096 + n0 + 4 * u);
                cc[s] = g_c[row * LL + (n0 >> 2) + u];
            }

            float4 acc[2][2];
#pragma unroll
            for (int mi = 0; mi < 2; mi++)
#pragma unroll
                for (int ni = 0; ni < 2; ni++) acc[mi][ni] = make_float4(0.f, 0.f, 0.f, 0.f);

            if (t >= 1) {   // t == 0: h = 0 -> matmul contributes nothing
                uint4 pr[8];
                a_load(Abh, LL, 0, tid, pr);
                a_store(As, tid, pr);
                __syncthreads();
                for (int kt = 0; kt < 8; ++kt) {
                    const int  cur  = kt & 1;
                    const bool more = (kt + 1 < 8);
                    if (more) a_load(Abh, LL, (kt + 1) * PBK2, tid, pr);
                    do_kk8<2>(As + cur * BM * ASTRH2, Ws, WSTRH_L, kt * PBK2, lane, wm, wn, acc);
                    if (more) a_store(As + ((kt + 1) & 1) * BM * ASTRH2, tid, pr);
                    __syncthreads();
                }
            }

#pragma unroll
            for (int mi = 0; mi < 2; mi++) {
#pragma unroll
                for (int ni = 0; ni < 2; ni++) {
                    const int r = wm * 32 + mi * 16 + (lane >> 2);
                    const int c = wn * 16 + ni * 8 + 2 * (lane & 3);
                    Cs[r * 36 + c]           = acc[mi][ni].x;
                    Cs[r * 36 + c + 1]       = acc[mi][ni].y;
                    Cs[(r + 8) * 36 + c]     = acc[mi][ni].z;
                    Cs[(r + 8) * 36 + c + 1] = acc[mi][ni].w;
                }
            }
            __syncthreads();

#pragma unroll
            for (int s = 0; s < 4; s++) {
                const int it  = tid + s * NTH;
                const int u   = it & 7;
                const int row = it >> 3;
                const int jg  = (n0 >> 2) + u;
                const float4 cv = *(const float4*)(Cs + row * 36 + 4 * u);
                const float ig = sigf(cv.x + xg[s].x);
                const float fg = sigf(cv.y + xg[s].y);
                const float gg = tanhf(cv.z + xg[s].z);
                const float og = sigf(cv.w + xg[s].w);
                const int ci = row * LL + jg;
                const float cn = fg * cc[s] + ig * gg;
                g_c[ci] = cn;
                const float hn = og * tanhf(cn);
                hoh[ci] = __float2half_rn(hn);
                g_hsh[((size_t)t * BB + row) * LL + jg] = __float2half_rn(hn);
            }

            bar_arrive(g_bar_lstm);
            if (t < TSTEPS - 1)
                wait_ge(g_bar_lstm, 128u * (unsigned)(t + 1));
        }
        fc_worker(smh, fcb, out);
    } else {
        fc_worker(smh, fcb, out);
    }
}

// ---------------- prep kernels ----------------
__global__ void prep_gru(const float* __restrict__ Wih, const float* __restrict__ Whh,
                         const float* __restrict__ bih, const float* __restrict__ bhh) {
    const int idx = blockIdx.x * blockDim.x + threadIdx.x;
    if (idx < 2048 * 512) {
        const int row = idx >> 9, k = idx & 511;
        const int j = row >> 2, g = row & 3;
        float wg, w1;
        if (g == 0)      { wg = Wih[j * 512 + k] + Whh[j * 512 + k];                 w1 = Whh[j * 512 + k]; }
        else if (g == 1) { wg = Wih[(512 + j) * 512 + k] + Whh[(512 + j) * 512 + k]; w1 = Whh[(512 + j) * 512 + k]; }
        else if (g == 2) { wg = Wih[(1024 + j) * 512 + k];                           w1 = 0.f; }
        else             { wg = Whh[(1024 + j) * 512 + k];                           w1 = wg; }
        g_Wgh[idx]  = __float2half_rn(wg);
        g_Wg1h[idx] = __float2half_rn(w1);
    }
    if (idx < 2048) {
        const int j = idx >> 2, g = idx & 3;
        float b;
        if (g == 0)      b = bih[j] + bhh[j];
        else if (g == 1) b = bih[512 + j] + bhh[512 + j];
        else if (g == 2) b = bih[1024 + j];
        else             b = bhh[1024 + j];
        g_bg[idx] = b;
    }
}

__global__ void prep_lstm(const float* __restrict__ Wih, const float* __restrict__ Whh,
                          const float* __restrict__ bih, const float* __restrict__ bhh,
                          const float* __restrict__ fcW) {
    const int idx = blockIdx.x * blockDim.x + threadIdx.x;
    if (idx < 4096 * 1024) {
        const int row = idx >> 10, k = idx & 1023;
        const int j = row >> 2, p = row & 3;
        g_Whhlh[idx] = __float2half_rn(Whh[(size_t)(p * 1024 + j) * 1024 + k]);
    }
    if (idx < 4096 * 512) {
        const int row = idx >> 9, k = idx & 511;
        const int j = row >> 2, p = row & 3;
        g_Wihlh[idx] = __float2half_rn(Wih[(size_t)(p * 1024 + j) * 512 + k]);
    }
    if (idx < 1024 * 1024) {
        g_fcWh[idx] = __float2half_rn(fcW[idx]);
    }
    if (idx < 4096) {
        const int j = idx >> 2, p = idx & 3;
        g_bl[idx] = bih[p * 1024 + j] + bhh[p * 1024 + j];
    }
}

// also fills Xg[0] = bl (seq[0] == 0)
__global__ void prep_zero(const float* __restrict__ z) {
    const int idx = blockIdx.x * blockDim.x + threadIdx.x;
    if (idx < BB * LL) { g_hh[idx] = __float2half_rn(0.f); g_c[idx] = 0.f; }
    if (idx < BB * HH) { g_zh[idx] = __float2half_rn(z[idx]); }
    if (idx < BB * 4096) { g_Xg[idx] = g_bl[idx & 4095]; }
    if (idx == 0) { g_bar_gru[0] = 0u; g_bar_lstm[0] = 0u; g_fc_cnt[0] = 0u; }
}

// ---------------- host launcher ----------------
extern "C" void kernel_launch(void* const* d_in, const int* in_sizes, int n_in,
                              void* d_out, int out_size) {
    const float* z    = (const float*)d_in[0];
    const float* gWih = (const float*)d_in[2];
    const float* gWhh = (const float*)d_in[3];
    const float* gbih = (const float*)d_in[4];
    const float* gbhh = (const float*)d_in[5];
    const float* lWih = (const float*)d_in[6];
    const float* lWhh = (const float*)d_in[7];
    const float* lbih = (const float*)d_in[8];
    const float* lbhh = (const float*)d_in[9];
    const float* fcW  = (const float*)d_in[10];
    const float* fcb  = (const float*)d_in[11];
    float* out = (float*)d_out;

    cudaFuncSetAttribute(gruxg_persist,  cudaFuncAttributeMaxDynamicSharedMemorySize, SMEM_A_KERN);
    cudaFuncSetAttribute(lstmfc_persist, cudaFuncAttributeMaxDynamicSharedMemorySize, SMEM_B_KERN);

    prep_gru <<<(2048 * 512 + 255) / 256, 256>>>(gWih, gWhh, gbih, gbhh);
    prep_lstm<<<(4096 * 1024 + 255) / 256, 256>>>(lWih, lWhh, lbih, lbhh, fcW);
    prep_zero<<<(BB * 4096 + 255) / 256, 256>>>(z);

    // Kernel A: GRU chain (64 CTAs) + overlapped XG (64 CTAs)
    gruxg_persist<<<128, NTH, SMEM_A_KERN>>>(z);

    // Kernel B: LSTM chain (128 CTAs) + FC work-steal (20 CTAs + post-chain join)
    lstmfc_persist<<<148, NTH, SMEM_B_KERN>>>(fcb, out);
}

// round 7
// speedup vs baseline: 1.3378x; 1.2657x over previous
#include <cuda_runtime.h>
#include <cuda_fp16.h>
#include <cstdint>
#include <cstddef>

// ---------------- problem constants ----------------
#define TSTEPS 256
#define BB 128      // batch
#define HH 512      // GRU hidden
#define LL 1024     // LSTM hidden
#define VV 1024     // vocab

// ---------------- config (R4-proven mainloop: PBK=64) ----------------
#define NTH 256
#define BM 128
#define PBK 64
#define ASTRH (PBK + 8)             // 72 halfs
#define WSTRH_G (HH + 8)            // 520 halfs
#define WSTRH_L (LL + 8)            // 1032 halfs
#define CSTR 68                     // fp32 staging stride (64 cols + pad)

// dynamic smem (halfs): role layouts
//  GRU : Ws[64][WSTRH_G]  + As[2][128][ASTRH]   = 66560 + 36864  = 103424 B
//  XG  : Ws[128][WSTRH_G] + As[2][128][ASTRH]   = 133120 + 36864 = 169984 B
//  LSTM: Ws[64][WSTRH_L]  + As[2][128][ASTRH]   = 132096 + 36864 = 168960 B
//  FC  : Bs[2][64][ASTRH] + As[2][128][ASTRH]   = 18432 + 36864  = 55296 B
#define SMEM_FUSED 169984
#define F_ATILE (2 * 64 * ASTRH)    // FC As offset (halfs)

// ---------------- persistent device scratch ----------------
__device__ __align__(256) __half g_Wgh  [2048 * 512];   // GRU combined W (t>=2), gate-interleaved
__device__ __align__(256) __half g_Wg1h [2048 * 512];   // GRU step-1 W (x=0 path)
__device__ __align__(256) float  g_bg   [2048];         // GRU combined bias
__device__ __align__(256) __half g_Wihlh[4096 * 512];   // LSTM Wih fp16, gate-interleaved
__device__ __align__(256) float  g_bl   [4096];         // LSTM bih+bhh, interleaved
__device__ __align__(256) __half g_Whhlh[4096 * 1024];  // LSTM Whh fp16, gate-interleaved
__device__ __align__(256) __half g_fcWh [1024 * 1024];  // fc weights fp16
__device__ __align__(256) float  g_x    [2 * BB * HH];  // GRU state fp32 ping-pong
__device__ __align__(256) __half g_xh   [2 * BB * HH];  // GRU state fp16 (operand)
__device__ __align__(256) __half g_zh   [BB * HH];      // half(z)
__device__ __align__(256) __half g_seqh [TSTEPS * BB * HH];          // relu(x_t) fp16
__device__ __align__(256) float  g_Xg   [(size_t)TSTEPS * BB * 4096];// LSTM input gates (+bias)
__device__ __align__(256) __half g_hh   [2 * BB * LL];  // LSTM h fp16 ping-pong
__device__ __align__(256) float  g_c    [BB * LL];      // LSTM c fp32
__device__ __align__(256) __half g_hsh  [(size_t)TSTEPS * BB * LL];  // LSTM outputs [T,B,L]
// barrier counters, each on its own 128B line
__device__ __align__(128) unsigned g_bar_gru[32];
__device__ __align__(128) unsigned g_bar_xg[32];
__device__ __align__(128) unsigned g_bar_lstm[32];
__device__ __align__(128) unsigned g_fc_cnt[32];

// ---------------- helpers ----------------
__device__ __forceinline__ void mma_f16(float4& d,
                                        uint32_t a0, uint32_t a1, uint32_t a2, uint32_t a3,
                                        uint32_t b0, uint32_t b1) {
    asm volatile(
        "mma.sync.aligned.m16n8k16.row.col.f32.f16.f16.f32 "
        "{%0,%1,%2,%3}, {%4,%5,%6,%7}, {%8,%9}, {%0,%1,%2,%3};\n"
        : "+f"(d.x), "+f"(d.y), "+f"(d.z), "+f"(d.w)
        : "r"(a0), "r"(a1), "r"(a2), "r"(a3), "r"(b0), "r"(b1));
}

__device__ __forceinline__ float sigf(float x) { return 1.0f / (1.0f + expf(-x)); }

// arrive: release-add (orders all prior writes), no full membar
__device__ __forceinline__ void bar_arrive(unsigned* bar) {
    __syncthreads();
    if (threadIdx.x == 0)
        asm volatile("red.release.gpu.global.add.u32 [%0], 1;" :: "l"(bar) : "memory");
}
// plain acquire spin (R4-proven; no nanosleep)
__device__ __forceinline__ void wait_ge(unsigned* bar, unsigned target) {
    if (threadIdx.x == 0) {
        unsigned v;
        do {
            asm volatile("ld.acquire.gpu.global.b32 %0, [%1];" : "=r"(v) : "l"(bar));
        } while (v < target);
    }
    __syncthreads();
}

// R4-proven A-tile loaders: 8 threads/row, contiguous 128B per row
__device__ __forceinline__ void a_load(const __half* __restrict__ A, int ldK, int k0,
                                       int tid, uint4* pr) {
    const int rL = tid >> 3, ch = (tid & 7) * 8;
#pragma unroll
    for (int i = 0; i < 4; i++)
        pr[i] = *(const uint4*)(A + (size_t)(rL + 32 * i) * ldK + k0 + ch);
}
__device__ __forceinline__ void a_store(__half* buf, int tid, const uint4* pr) {
    const int rL = tid >> 3, ch = (tid & 7) * 8;
#pragma unroll
    for (int i = 0; i < 4; i++)
        *(uint4*)(buf + (rL + 32 * i) * ASTRH + ch) = pr[i];
}

// one PBK=64 k-slab of mma (4 kk iters). B rows at stride wstr, k offset kg0.
template <int NI>
__device__ __forceinline__ void do_kk4(const __half* __restrict__ Ac,
                                       const __half* __restrict__ Bbase,
                                       int wstr, int kg0,
                                       int lane, int wm, int wn,
                                       float4 (&acc)[2][NI]) {
#pragma unroll
    for (int kk = 0; kk < 4; kk++) {
        const int kb = kk * 16 + 2 * (lane & 3);
        uint32_t af[2][4];
#pragma unroll
        for (int mi = 0; mi < 2; mi++) {
            const __half* ap = Ac + (wm * 32 + mi * 16 + (lane >> 2)) * ASTRH + kb;
            af[mi][0] = *(const uint32_t*)(ap);
            af[mi][1] = *(const uint32_t*)(ap + 8 * ASTRH);
            af[mi][2] = *(const uint32_t*)(ap + 8);
            af[mi][3] = *(const uint32_t*)(ap + 8 * ASTRH + 8);
        }
#pragma unroll
        for (int ni = 0; ni < NI; ni++) {
            const __half* wp = Bbase + (size_t)(wn * (NI * 8) + ni * 8 + (lane >> 2)) * wstr + kg0 + kb;
            const uint32_t b0 = *(const uint32_t*)(wp);
            const uint32_t b1 = *(const uint32_t*)(wp + 8);
#pragma unroll
            for (int mi = 0; mi < 2; mi++)
                mma_f16(acc[mi][ni], af[mi][0], af[mi][1], af[mi][2], af[mi][3], b0, b1);
        }
    }
}

// ============================================================================
// FC work-steal: logits tile [128 x 64] = hs_t @ fcW^T + fcb
// ============================================================================
__device__ void fc_worker(__half* smh, const float* __restrict__ fcb,
                          float* __restrict__ out) {
    __shared__ int s_tile;
    __half* Bs = smh;               // [2][64][ASTRH]
    __half* As = smh + F_ATILE;     // [2][128][ASTRH]

    const int tid  = threadIdx.x;
    const int lane = tid & 31;
    const int wid  = tid >> 5;
    const int wm   = wid & 3;
    const int wn   = wid >> 2;

    while (true) {
        __syncthreads();
        if (tid == 0) s_tile = (int)atomicAdd(&g_fc_cnt[0], 1u);
        __syncthreads();
        const int tile = s_tile;
        if (tile >= TSTEPS * 16) return;
        const int t  = tile >> 4;
        const int n0 = (tile & 15) * 64;
        wait_ge(g_bar_lstm, 64u * (unsigned)(t + 1));

        const __half* Abh = g_hsh  + (size_t)t * BB * LL;
        const __half* Wb  = g_fcWh + (size_t)n0 * LL;

        float4 acc[2][4];
#pragma unroll
        for (int mi = 0; mi < 2; mi++)
#pragma unroll
            for (int ni = 0; ni < 4; ni++) acc[mi][ni] = make_float4(0.f, 0.f, 0.f, 0.f);

        uint4 pr[4], qr[2];
        a_load(Abh, LL, 0, tid, pr);
        {
            const int r = tid >> 2, cb = (tid & 3) * 8;
#pragma unroll
            for (int j = 0; j < 2; j++)
                qr[j] = *(const uint4*)(Wb + (size_t)r * LL + cb + j * 32);
        }
        a_store(As, tid, pr);
        {
            const int r = tid >> 2, cb = (tid & 3) * 8;
#pragma unroll
            for (int j = 0; j < 2; j++)
                *(uint4*)(Bs + r * ASTRH + cb + j * 32) = qr[j];
        }
        __syncthreads();

        for (int kt = 0; kt < 16; ++kt) {
            const int  cur  = kt & 1;
            const bool more = (kt + 1 < 16);
            if (more) {
                const int k0 = (kt + 1) * PBK;
                a_load(Abh, LL, k0, tid, pr);
                const int r = tid >> 2, cb = (tid & 3) * 8;
#pragma unroll
                for (int j = 0; j < 2; j++)
                    qr[j] = *(const uint4*)(Wb + (size_t)r * LL + k0 + cb + j * 32);
            }
            do_kk4<4>(As + cur * BM * ASTRH, Bs + cur * 64 * ASTRH,
                      ASTRH, 0, lane, wm, wn, acc);
            if (more) {
                const int nxt = cur ^ 1;
                a_store(As + nxt * BM * ASTRH, tid, pr);
                const int r = tid >> 2, cb = (tid & 3) * 8;
#pragma unroll
                for (int j = 0; j < 2; j++)
                    *(uint4*)(Bs + nxt * 64 * ASTRH + r * ASTRH + cb + j * 32) = qr[j];
            }
            __syncthreads();
        }

#pragma unroll
        for (int mi = 0; mi < 2; mi++) {
#pragma unroll
            for (int ni = 0; ni < 4; ni++) {
                const int r   = wm * 32 + mi * 16 + (lane >> 2);
                const int col = n0 + wn * 32 + ni * 8 + 2 * (lane & 3);
                const float b0 = fcb[col], b1 = fcb[col + 1];
                float* o0 = out + ((size_t)r * TSTEPS + t) * VV + col;
                float* o1 = out + ((size_t)(r + 8) * TSTEPS + t) * VV + col;
                *(float2*)o0 = make_float2(acc[mi][ni].x + b0, acc[mi][ni].y + b1);
                *(float2*)o1 = make_float2(acc[mi][ni].z + b0, acc[mi][ni].w + b1);
            }
        }
    }
}

// ============================================================================
// Fused pipelined kernel, grid = 148 (all CTAs co-resident):
//   bid 0-31:    GRU chain, 64 cols each
//   bid 32-63:   XG, 128 cols each (consumes seq[t] one step behind GRU)
//   bid 64-127:  LSTM chain, 64 cols each (consumes Xg[t])
//   bid 128-147: FC work-steal (plus all chain CTAs join at the end)
// ============================================================================
__global__ void __launch_bounds__(NTH)
fused_persist(const float* __restrict__ z, const float* __restrict__ fcb,
              float* __restrict__ out) {
    extern __shared__ __half smh[];
    const int tid  = threadIdx.x;
    const int lane = tid & 31;
    const int wid  = tid >> 5;
    const int wm   = wid & 3;
    const int wn   = wid >> 2;
    const int bid  = blockIdx.x;

    if (bid < 32) {
        // ================= GRU chain: 64 cols (16 units) =================
        __half* Ws = smh;                     // [64][WSTRH_G]
        __half* As = smh + 64 * WSTRH_G;      // [2][128][ASTRH]
        float*  Cs = (float*)As;              // staging, stride CSTR
        const int n0 = bid * 64;

        for (int i = tid; i < 64 * 64; i += NTH) {
            const int r = i >> 6, c = (i & 63) * 8;
            *(uint4*)(Ws + r * WSTRH_G + c) = *(const uint4*)(g_Wg1h + (size_t)(n0 + r) * HH + c);
        }
        __syncthreads();

        for (int t = 1; t < TSTEPS; ++t) {
            const __half* Abh  = (t == 1) ? g_zh : g_xh + (size_t)((t - 1) & 1) * BB * HH;
            const float*  hp32 = (t == 1) ? z    : g_x  + (size_t)((t - 1) & 1) * BB * HH;
            float*  xo32 = g_x    + (size_t)(t & 1) * BB * HH;
            __half* xoh  = g_xh   + (size_t)(t & 1) * BB * HH;
            __half* so   = g_seqh + (size_t)t * BB * HH;

            float hp[8];
#pragma unroll
            for (int s = 0; s < 8; s++) {
                const int it = tid + s * NTH;
                hp[s] = hp32[(size_t)(it >> 4) * HH + (n0 >> 2) + (it & 15)];
            }

            float4 acc[2][4];
#pragma unroll
            for (int mi = 0; mi < 2; mi++)
#pragma unroll
                for (int ni = 0; ni < 4; ni++) acc[mi][ni] = make_float4(0.f, 0.f, 0.f, 0.f);

            uint4 pr[4];
            a_load(Abh, HH, 0, tid, pr);
            a_store(As, tid, pr);
            __syncthreads();
            for (int kt = 0; kt < 8; ++kt) {
                const int  cur  = kt & 1;
                const bool more = (kt + 1 < 8);
                if (more) a_load(Abh, HH, (kt + 1) * PBK, tid, pr);
                do_kk4<4>(As + cur * BM * ASTRH, Ws, WSTRH_G, kt * PBK, lane, wm, wn, acc);
                if (more) a_store(As + ((kt + 1) & 1) * BM * ASTRH, tid, pr);
                __syncthreads();
            }

#pragma unroll
            for (int mi = 0; mi < 2; mi++) {
#pragma unroll
                for (int ni = 0; ni < 4; ni++) {
                    const int r = wm * 32 + mi * 16 + (lane >> 2);
                    const int c = wn * 32 + ni * 8 + 2 * (lane & 3);
                    const float b0 = g_bg[n0 + c], b1 = g_bg[n0 + c + 1];
                    Cs[r * CSTR + c]           = acc[mi][ni].x + b0;
                    Cs[r * CSTR + c + 1]       = acc[mi][ni].y + b1;
                    Cs[(r + 8) * CSTR + c]     = acc[mi][ni].z + b0;
                    Cs[(r + 8) * CSTR + c + 1] = acc[mi][ni].w + b1;
                }
            }
            __syncthreads();

#pragma unroll
            for (int s = 0; s < 8; s++) {
                const int it  = tid + s * NTH;
                const int u   = it & 15;
                const int row = it >> 4;
                const int jg  = (n0 >> 2) + u;
                const float4 cv = *(const float4*)(Cs + row * CSTR + 4 * u);
                const float rg = sigf(cv.x);
                const float zg = sigf(cv.y);
                const float nn = tanhf(cv.z + rg * cv.w);
                const float xn = (1.f - zg) * nn + zg * hp[s];
                const int oi = row * HH + jg;
                xo32[oi] = xn;
                xoh[oi]  = __float2half_rn(xn);
                so[oi]   = __float2half_rn(fmaxf(xn, 0.f));
            }

            bar_arrive(g_bar_gru);
            if (t < TSTEPS - 1) {
                wait_ge(g_bar_gru, 32u * (unsigned)t);
                if (t == 1) {   // swap to combined weights for t >= 2
                    for (int i = tid; i < 64 * 64; i += NTH) {
                        const int r = i >> 6, c = (i & 63) * 8;
                        *(uint4*)(Ws + r * WSTRH_G + c) =
                            *(const uint4*)(g_Wgh + (size_t)(n0 + r) * HH + c);
                    }
                    __syncthreads();
                }
            }
        }
        fc_worker(smh, fcb, out);

    } else if (bid < 64) {
        // ================= XG: Xg[t] = seq[t] @ Wih^T + bl, 128 cols =================
        __half* Ws = smh;                     // [128][WSTRH_G]
        __half* As = smh + 128 * WSTRH_G;     // [2][128][ASTRH]
        const int n0 = (bid - 32) * 128;

        for (int i = tid; i < 128 * 64; i += NTH) {
            const int r = i >> 6, c = (i & 63) * 8;
            *(uint4*)(Ws + r * WSTRH_G + c) = *(const uint4*)(g_Wihlh + (size_t)(n0 + r) * HH + c);
        }
        __syncthreads();

        for (int t = 1; t < TSTEPS; ++t) {
            wait_ge(g_bar_gru, 32u * (unsigned)t);
            const __half* Abh = g_seqh + (size_t)t * BB * HH;

            float4 acc[2][2][4];    // [np][mi][ni]
#pragma unroll
            for (int np = 0; np < 2; np++)
#pragma unroll
                for (int mi = 0; mi < 2; mi++)
#pragma unroll
                    for (int ni = 0; ni < 4; ni++)
                        acc[np][mi][ni] = make_float4(0.f, 0.f, 0.f, 0.f);

            uint4 pr[4];
            a_load(Abh, HH, 0, tid, pr);
            a_store(As, tid, pr);
            __syncthreads();
            for (int kt = 0; kt < 8; ++kt) {
                const int  cur  = kt & 1;
                const bool more = (kt + 1 < 8);
                if (more) a_load(Abh, HH, (kt + 1) * PBK, tid, pr);
                do_kk4<4>(As + cur * BM * ASTRH, Ws, WSTRH_G, kt * PBK,
                          lane, wm, wn, acc[0]);
                do_kk4<4>(As + cur * BM * ASTRH, Ws + 64 * WSTRH_G, WSTRH_G, kt * PBK,
                          lane, wm, wn, acc[1]);
                if (more) a_store(As + ((kt + 1) & 1) * BM * ASTRH, tid, pr);
                __syncthreads();
            }

#pragma unroll
            for (int np = 0; np < 2; np++) {
#pragma unroll
                for (int mi = 0; mi < 2; mi++) {
#pragma unroll
                    for (int ni = 0; ni < 4; ni++) {
                        const int r   = wm * 32 + mi * 16 + (lane >> 2);
                        const int col = n0 + np * 64 + wn * 32 + ni * 8 + 2 * (lane & 3);
                        const float b0 = g_bl[col], b1 = g_bl[col + 1];
                        float* o0 = g_Xg + ((size_t)t * BB + r) * 4096 + col;
                        float* o1 = g_Xg + ((size_t)t * BB + r + 8) * 4096 + col;
                        *(float2*)o0 = make_float2(acc[np][mi][ni].x + b0, acc[np][mi][ni].y + b1);
                        *(float2*)o1 = make_float2(acc[np][mi][ni].z + b0, acc[np][mi][ni].w + b1);
                    }
                }
            }
            bar_arrive(g_bar_xg);
        }
        fc_worker(smh, fcb, out);

    } else if (bid < 128) {
        // ================= LSTM chain: 64 cols (16 units) =================
        __half* Ws = smh;                     // [64][WSTRH_L]
        __half* As = smh + 64 * WSTRH_L;      // [2][128][ASTRH]
        float*  Cs = (float*)As;              // staging, stride CSTR
        const int n0 = (bid - 64) * 64;

        for (int i = tid; i < 64 * 128; i += NTH) {
            const int r = i >> 7, c = (i & 127) * 8;
            *(uint4*)(Ws + r * WSTRH_L + c) = *(const uint4*)(g_Whhlh + (size_t)(n0 + r) * LL + c);
        }
        __syncthreads();

        for (int t = 0; t < TSTEPS; ++t) {
            if (t >= 1) {
                wait_ge(g_bar_xg,   32u * (unsigned)t);   // Xg[t] ready
                wait_ge(g_bar_lstm, 64u * (unsigned)t);   // h[t-1] ready
            }
            const __half* Abh = g_hh + (size_t)(t & 1) * BB * LL;
            __half* hoh       = g_hh + (size_t)((t + 1) & 1) * BB * LL;

            float4 acc[2][4];
#pragma unroll
            for (int mi = 0; mi < 2; mi++)
#pragma unroll
                for (int ni = 0; ni < 4; ni++) acc[mi][ni] = make_float4(0.f, 0.f, 0.f, 0.f);

            if (t >= 1) {   // t == 0: h = 0 -> matmul contributes nothing
                uint4 pr[4];
                a_load(Abh, LL, 0, tid, pr);
                a_store(As, tid, pr);
                __syncthreads();
                for (int kt = 0; kt < 16; ++kt) {
                    const int  cur  = kt & 1;
                    const bool more = (kt + 1 < 16);
                    if (more) a_load(Abh, LL, (kt + 1) * PBK, tid, pr);
                    do_kk4<4>(As + cur * BM * ASTRH, Ws, WSTRH_L, kt * PBK, lane, wm, wn, acc);
                    if (more) a_store(As + ((kt + 1) & 1) * BM * ASTRH, tid, pr);
                    __syncthreads();
                }
            }

#pragma unroll
            for (int mi = 0; mi < 2; mi++) {
#pragma unroll
                for (int ni = 0; ni < 4; ni++) {
                    const int r = wm * 32 + mi * 16 + (lane >> 2);
                    const int c = wn * 32 + ni * 8 + 2 * (lane & 3);
                    Cs[r * CSTR + c]           = acc[mi][ni].x;
                    Cs[r * CSTR + c + 1]       = acc[mi][ni].y;
                    Cs[(r + 8) * CSTR + c]     = acc[mi][ni].z;
                    Cs[(r + 8) * CSTR + c + 1] = acc[mi][ni].w;
                }
            }
            __syncthreads();

#pragma unroll
            for (int s = 0; s < 8; s++) {
                const int it  = tid + s * NTH;
                const int u   = it & 15;
                const int row = it >> 4;
                const int jg  = (n0 >> 2) + u;
                const float4 cv = *(const float4*)(Cs + row * CSTR + 4 * u);
                const float4 xg = *(const float4*)(g_Xg + ((size_t)t * BB + row) * 4096 + n0 + 4 * u);
                const float ig = sigf(cv.x + xg.x);
                const float fg = sigf(cv.y + xg.y);
                const float gg = tanhf(cv.z + xg.z);
                const float og = sigf(cv.w + xg.w);
                const int ci = row * LL + jg;
                const float cn = fg * g_c[ci] + ig * gg;
                g_c[ci] = cn;
                const float hn = og * tanhf(cn);
                hoh[ci] = __float2half_rn(hn);
                g_hsh[((size_t)t * BB + row) * LL + jg] = __float2half_rn(hn);
            }

            bar_arrive(g_bar_lstm);
        }
        fc_worker(smh, fcb, out);

    } else {
        fc_worker(smh, fcb, out);
    }
}

// ---------------- prep kernels ----------------
__global__ void prep_gru(const float* __restrict__ Wih, const float* __restrict__ Whh,
                         const float* __restrict__ bih, const float* __restrict__ bhh) {
    const int idx = blockIdx.x * blockDim.x + threadIdx.x;
    if (idx < 2048 * 512) {
        const int row = idx >> 9, k = idx & 511;
        const int j = row >> 2, g = row & 3;
        float wg, w1;
        if (g == 0)      { wg = Wih[j * 512 + k] + Whh[j * 512 + k];                 w1 = Whh[j * 512 + k]; }
        else if (g == 1) { wg = Wih[(512 + j) * 512 + k] + Whh[(512 + j) * 512 + k]; w1 = Whh[(512 + j) * 512 + k]; }
        else if (g == 2) { wg = Wih[(1024 + j) * 512 + k];                           w1 = 0.f; }
        else             { wg = Whh[(1024 + j) * 512 + k];                           w1 = wg; }
        g_Wgh[idx]  = __float2half_rn(wg);
        g_Wg1h[idx] = __float2half_rn(w1);
    }
    if (idx < 2048) {
        const int j = idx >> 2, g = idx & 3;
        float b;
        if (g == 0)      b = bih[j] + bhh[j];
        else if (g == 1) b = bih[512 + j] + bhh[512 + j];
        else if (g == 2) b = bih[1024 + j];
        else             b = bhh[1024 + j];
        g_bg[idx] = b;
    }
}

__global__ void prep_lstm(const float* __restrict__ Wih, const float* __restrict__ Whh,
                          const float* __restrict__ bih, const float* __restrict__ bhh,
                          const float* __restrict__ fcW) {
    const int idx = blockIdx.x * blockDim.x + threadIdx.x;
    if (idx < 4096 * 1024) {
        const int row = idx >> 10, k = idx & 1023;
        const int j = row >> 2, p = row & 3;
        g_Whhlh[idx] = __float2half_rn(Whh[(size_t)(p * 1024 + j) * 1024 + k]);
    }
    if (idx < 4096 * 512) {
        const int row = idx >> 9, k = idx & 511;
        const int j = row >> 2, p = row & 3;
        g_Wihlh[idx] = __float2half_rn(Wih[(size_t)(p * 1024 + j) * 512 + k]);
    }
    if (idx < 1024 * 1024) {
        g_fcWh[idx] = __float2half_rn(fcW[idx]);
    }
    if (idx < 4096) {
        const int j = idx >> 2, p = idx & 3;
        g_bl[idx] = bih[p * 1024 + j] + bhh[p * 1024 + j];
    }
}

// zero states, half(z), Xg[0] = bl (seq[0] == 0), reset barriers
__global__ void prep_zero(const float* __restrict__ z) {
    const int idx = blockIdx.x * blockDim.x + threadIdx.x;
    if (idx < BB * LL) { g_hh[idx] = __float2half_rn(0.f); g_c[idx] = 0.f; }
    if (idx < BB * HH) { g_zh[idx] = __float2half_rn(z[idx]); }
    if (idx < BB * 4096) { g_Xg[idx] = g_bl[idx & 4095]; }
    if (idx == 0) { g_bar_gru[0] = 0u; g_bar_xg[0] = 0u; g_bar_lstm[0] = 0u; g_fc_cnt[0] = 0u; }
}

// ---------------- host launcher ----------------
extern "C" void kernel_launch(void* const* d_in, const int* in_sizes, int n_in,
                              void* d_out, int out_size) {
    const float* z    = (const float*)d_in[0];
    const float* gWih = (const float*)d_in[2];
    const float* gWhh = (const float*)d_in[3];
    const float* gbih = (const float*)d_in[4];
    const float* gbhh = (const float*)d_in[5];
    const float* lWih = (const float*)d_in[6];
    const float* lWhh = (const float*)d_in[7];
    const float* lbih = (const float*)d_in[8];
    const float* lbhh = (const float*)d_in[9];
    const float* fcW  = (const float*)d_in[10];
    const float* fcb  = (const float*)d_in[11];
    float* out = (float*)d_out;

    cudaFuncSetAttribute(fused_persist, cudaFuncAttributeMaxDynamicSharedMemorySize, SMEM_FUSED);

    prep_gru <<<(2048 * 512 + 255) / 256, 256>>>(gWih, gWhh, gbih, gbhh);
    prep_lstm<<<(4096 * 1024 + 255) / 256, 256>>>(lWih, lWhh, lbih, lbhh, fcW);
    prep_zero<<<(BB * 4096 + 255) / 256, 256>>>(z);

    // one fused persistent kernel: GRU | XG | LSTM | FC truly pipelined on
    // disjoint CTA sets (32 + 32 + 64 + 20 = 148, all co-resident)
    fused_persist<<<148, NTH, SMEM_FUSED>>>(z, fcb, out);
}

// round 8
// speedup vs baseline: 1.7762x; 1.3277x over previous
#include <cuda_runtime.h>
#include <cuda_fp16.h>
#include <cstdint>
#include <cstddef>

// ---------------- problem constants ----------------
#define TSTEPS 256
#define BB 128      // batch
#define HH 512      // GRU hidden
#define LL 1024     // LSTM hidden
#define VV 1024     // vocab

// ---------------- config ----------------
#define NTH 512
#define BM 128
#define PBK 64
#define ASTRH (PBK + 8)             // 72 halfs
#define WSTRH_G (HH + 8)            // 520 halfs
#define WSTRH_L (LL + 8)            // 1032 halfs
#define CSTR 68                     // fp32 staging stride (64 cols + pad)

// dynamic smem (halfs):
//  GRU : Ws[64][WSTRH_G]  + As[2][128][ASTRH]  = 103424 B
//  XG  : Ws[128][WSTRH_G] + As[2][128][ASTRH]  = 169984 B
//  LSTM: Ws[64][WSTRH_L]  + As[2][128][ASTRH]  = 168960 B
//  FC  : Bs[2][64][ASTRH] + As[2][128][ASTRH]  = 55296 B
#define SMEM_FUSED 169984
#define F_ATILE (2 * 64 * ASTRH)    // FC As offset (halfs)

// ---------------- persistent device scratch ----------------
__device__ __align__(256) __half g_Wgh  [2048 * 512];   // GRU combined W (t>=2), gate-interleaved
__device__ __align__(256) __half g_Wg1h [2048 * 512];   // GRU step-1 W (x=0 path)
__device__ __align__(256) float  g_bg   [2048];         // GRU combined bias
__device__ __align__(256) __half g_Wihlh[4096 * 512];   // LSTM Wih fp16, gate-interleaved
__device__ __align__(256) float  g_bl   [4096];         // LSTM bih+bhh, interleaved
__device__ __align__(256) __half g_Whhlh[4096 * 1024];  // LSTM Whh fp16, gate-interleaved
__device__ __align__(256) __half g_fcWh [1024 * 1024];  // fc weights fp16
__device__ __align__(256) float  g_x    [2 * BB * HH];  // GRU state fp32 ping-pong
__device__ __align__(256) __half g_xh   [2 * BB * HH];  // GRU state fp16 (operand)
__device__ __align__(256) __half g_zh   [BB * HH];      // half(z)
__device__ __align__(256) __half g_seqh [TSTEPS * BB * HH];          // relu(x_t) fp16
__device__ __align__(256) float  g_Xg   [(size_t)TSTEPS * BB * 4096];// LSTM input gates (+bias)
__device__ __align__(256) __half g_hh   [2 * BB * LL];  // LSTM h fp16 ping-pong
__device__ __align__(256) float  g_c    [BB * LL];      // LSTM c fp32
__device__ __align__(256) __half g_hsh  [(size_t)TSTEPS * BB * LL];  // LSTM outputs [T,B,L]
// barrier counters, each on its own 128B line
__device__ __align__(128) unsigned g_bar_gru[32];
__device__ __align__(128) unsigned g_bar_xg[32];
__device__ __align__(128) unsigned g_bar_lstm[32];
__device__ __align__(128) unsigned g_fc_cnt[32];

// ---------------- helpers ----------------
__device__ __forceinline__ void mma_f16(float4& d,
                                        uint32_t a0, uint32_t a1, uint32_t a2, uint32_t a3,
                                        uint32_t b0, uint32_t b1) {
    asm volatile(
        "mma.sync.aligned.m16n8k16.row.col.f32.f16.f16.f32 "
        "{%0,%1,%2,%3}, {%4,%5,%6,%7}, {%8,%9}, {%0,%1,%2,%3};\n"
        : "+f"(d.x), "+f"(d.y), "+f"(d.z), "+f"(d.w)
        : "r"(a0), "r"(a1), "r"(a2), "r"(a3), "r"(b0), "r"(b1));
}

__device__ __forceinline__ float sigf(float x) { return 1.0f / (1.0f + expf(-x)); }

// arrive: release-add (orders all prior writes), no full membar
__device__ __forceinline__ void bar_arrive(unsigned* bar) {
    __syncthreads();
    if (threadIdx.x == 0)
        asm volatile("red.release.gpu.global.add.u32 [%0], 1;" :: "l"(bar) : "memory");
}
// acquire spin
__device__ __forceinline__ void wait_ge(unsigned* bar, unsigned target) {
    if (threadIdx.x == 0) {
        unsigned v;
        do {
            asm volatile("ld.acquire.gpu.global.b32 %0, [%1];" : "=r"(v) : "l"(bar));
        } while (v < target);
    }
    __syncthreads();
}
// combined two-barrier wait (one poll loop)
__device__ __forceinline__ void wait_ge2(unsigned* barA, unsigned tA,
                                         unsigned* barB, unsigned tB) {
    if (threadIdx.x == 0) {
        unsigned va, vb;
        do {
            asm volatile("ld.acquire.gpu.global.b32 %0, [%1];" : "=r"(va) : "l"(barA));
            asm volatile("ld.acquire.gpu.global.b32 %0, [%1];" : "=r"(vb) : "l"(barB));
        } while (va < tA || vb < tB);
    }
    __syncthreads();
}

// A-tile [128][64 halfs] loaders, 512 threads: 8 threads/row, 2 rows per thread
__device__ __forceinline__ void a_load(const __half* __restrict__ A, int ldK, int k0,
                                       int tid, uint4* pr) {
    const int rL = tid >> 3, ch = (tid & 7) * 8;
#pragma unroll
    for (int i = 0; i < 2; i++)
        pr[i] = *(const uint4*)(A + (size_t)(rL + 64 * i) * ldK + k0 + ch);
}
__device__ __forceinline__ void a_store(__half* buf, int tid, const uint4* pr) {
    const int rL = tid >> 3, ch = (tid & 7) * 8;
#pragma unroll
    for (int i = 0; i < 2; i++)
        *(uint4*)(buf + (rL + 64 * i) * ASTRH + ch) = pr[i];
}

// one PBK=64 k-slab of mma (4 kk iters). Warp grid 4x4: wm rows, wn covers NI*8 cols.
template <int NI>
__device__ __forceinline__ void do_kk4(const __half* __restrict__ Ac,
                                       const __half* __restrict__ Bbase,
                                       int wstr, int kg0,
                                       int lane, int wm, int wn,
                                       float4 (&acc)[2][NI]) {
#pragma unroll
    for (int kk = 0; kk < 4; kk++) {
        const int kb = kk * 16 + 2 * (lane & 3);
        uint32_t af[2][4];
#pragma unroll
        for (int mi = 0; mi < 2; mi++) {
            const __half* ap = Ac + (wm * 32 + mi * 16 + (lane >> 2)) * ASTRH + kb;
            af[mi][0] = *(const uint32_t*)(ap);
            af[mi][1] = *(const uint32_t*)(ap + 8 * ASTRH);
            af[mi][2] = *(const uint32_t*)(ap + 8);
            af[mi][3] = *(const uint32_t*)(ap + 8 * ASTRH + 8);
        }
#pragma unroll
        for (int ni = 0; ni < NI; ni++) {
            const __half* wp = Bbase + (size_t)(wn * (NI * 8) + ni * 8 + (lane >> 2)) * wstr + kg0 + kb;
            const uint32_t b0 = *(const uint32_t*)(wp);
            const uint32_t b1 = *(const uint32_t*)(wp + 8);
#pragma unroll
            for (int mi = 0; mi < 2; mi++)
                mma_f16(acc[mi][ni], af[mi][0], af[mi][1], af[mi][2], af[mi][3], b0, b1);
        }
    }
}

// ============================================================================
// FC work-steal: logits tile [128 x 64] = hs_t @ fcW^T + fcb
// ============================================================================
__device__ void fc_worker(__half* smh, const float* __restrict__ fcb,
                          float* __restrict__ out) {
    __shared__ int s_tile;
    __half* Bs = smh;               // [2][64][ASTRH]
    __half* As = smh + F_ATILE;     // [2][128][ASTRH]

    const int tid  = threadIdx.x;
    const int lane = tid & 31;
    const int wid  = tid >> 5;
    const int wm   = wid & 3;
    const int wn   = wid >> 2;      // 0..3, 16 cols each

    while (true) {
        __syncthreads();
        if (tid == 0) s_tile = (int)atomicAdd(&g_fc_cnt[0], 1u);
        __syncthreads();
        const int tile = s_tile;
        if (tile >= TSTEPS * 16) return;
        const int t  = tile >> 4;
        const int n0 = (tile & 15) * 64;
        wait_ge(g_bar_lstm, 64u * (unsigned)(t + 1));

        const __half* Abh = g_hsh  + (size_t)t * BB * LL;
        const __half* Wb  = g_fcWh + (size_t)n0 * LL;

        float4 acc[2][2];
#pragma unroll
        for (int mi = 0; mi < 2; mi++)
#pragma unroll
            for (int ni = 0; ni < 2; ni++) acc[mi][ni] = make_float4(0.f, 0.f, 0.f, 0.f);

        uint4 pr[2], qr;
        a_load(Abh, LL, 0, tid, pr);
        {
            const int r = tid >> 3, cb = (tid & 7) * 8;
            qr = *(const uint4*)(Wb + (size_t)r * LL + cb);
        }
        a_store(As, tid, pr);
        {
            const int r = tid >> 3, cb = (tid & 7) * 8;
            *(uint4*)(Bs + r * ASTRH + cb) = qr;
        }
        __syncthreads();

        for (int kt = 0; kt < 16; ++kt) {
            const int  cur  = kt & 1;
            const bool more = (kt + 1 < 16);
            if (more) {
                const int k0 = (kt + 1) * PBK;
                a_load(Abh, LL, k0, tid, pr);
                const int r = tid >> 3, cb = (tid & 7) * 8;
                qr = *(const uint4*)(Wb + (size_t)r * LL + k0 + cb);
            }
            do_kk4<2>(As + cur * BM * ASTRH, Bs + cur * 64 * ASTRH,
                      ASTRH, 0, lane, wm, wn, acc);
            if (more) {
                const int nxt = cur ^ 1;
                a_store(As + nxt * BM * ASTRH, tid, pr);
                const int r = tid >> 3, cb = (tid & 7) * 8;
                *(uint4*)(Bs + nxt * 64 * ASTRH + r * ASTRH + cb) = qr;
            }
            __syncthreads();
        }

#pragma unroll
        for (int mi = 0; mi < 2; mi++) {
#pragma unroll
            for (int ni = 0; ni < 2; ni++) {
                const int r   = wm * 32 + mi * 16 + (lane >> 2);
                const int col = n0 + wn * 16 + ni * 8 + 2 * (lane & 3);
                const float b0 = fcb[col], b1 = fcb[col + 1];
                float* o0 = out + ((size_t)r * TSTEPS + t) * VV + col;
                float* o1 = out + ((size_t)(r + 8) * TSTEPS + t) * VV + col;
                *(float2*)o0 = make_float2(acc[mi][ni].x + b0, acc[mi][ni].y + b1);
                *(float2*)o1 = make_float2(acc[mi][ni].z + b0, acc[mi][ni].w + b1);
            }
        }
    }
}

// ============================================================================
// Fused pipelined kernel, grid = 148 (all CTAs co-resident, 512 thr each):
//   bid 0-31:    GRU chain, 64 cols each
//   bid 32-63:   XG, 128 cols each (one step behind GRU)
//   bid 64-127:  LSTM chain, 64 cols each (consumes Xg[t])
//   bid 128-147: FC work-steal (chain CTAs join at the end)
// ============================================================================
__global__ void __launch_bounds__(NTH)
fused_persist(const float* __restrict__ z, const float* __restrict__ fcb,
              float* __restrict__ out) {
    extern __shared__ __half smh[];
    const int tid  = threadIdx.x;
    const int lane = tid & 31;
    const int wid  = tid >> 5;
    const int wm   = wid & 3;
    const int wn   = wid >> 2;      // 0..3
    const int bid  = blockIdx.x;

    if (bid < 32) {
        // ================= GRU chain: 64 cols (16 units) =================
        __half* Ws = smh;                     // [64][WSTRH_G]
        __half* As = smh + 64 * WSTRH_G;      // [2][128][ASTRH]
        float*  Cs = (float*)As;              // staging, stride CSTR
        const int n0 = bid * 64;

        for (int i = tid; i < 64 * 64; i += NTH) {
            const int r = i >> 6, c = (i & 63) * 8;
            *(uint4*)(Ws + r * WSTRH_G + c) = *(const uint4*)(g_Wg1h + (size_t)(n0 + r) * HH + c);
        }
        __syncthreads();

        for (int t = 1; t < TSTEPS; ++t) {
            const __half* Abh  = (t == 1) ? g_zh : g_xh + (size_t)((t - 1) & 1) * BB * HH;
            const float*  hp32 = (t == 1) ? z    : g_x  + (size_t)((t - 1) & 1) * BB * HH;
            float*  xo32 = g_x    + (size_t)(t & 1) * BB * HH;
            __half* xoh  = g_xh   + (size_t)(t & 1) * BB * HH;
            __half* so   = g_seqh + (size_t)t * BB * HH;

            float hp[4];
#pragma unroll
            for (int s = 0; s < 4; s++) {
                const int it = tid + s * NTH;
                hp[s] = hp32[(size_t)(it >> 4) * HH + (n0 >> 2) + (it & 15)];
            }

            float4 acc[2][2];
#pragma unroll
            for (int mi = 0; mi < 2; mi++)
#pragma unroll
                for (int ni = 0; ni < 2; ni++) acc[mi][ni] = make_float4(0.f, 0.f, 0.f, 0.f);

            uint4 pr[2];
            a_load(Abh, HH, 0, tid, pr);
            a_store(As, tid, pr);
            __syncthreads();
            for (int kt = 0; kt < 8; ++kt) {
                const int  cur  = kt & 1;
                const bool more = (kt + 1 < 8);
                if (more) a_load(Abh, HH, (kt + 1) * PBK, tid, pr);
                do_kk4<2>(As + cur * BM * ASTRH, Ws, WSTRH_G, kt * PBK, lane, wm, wn, acc);
                if (more) a_store(As + ((kt + 1) & 1) * BM * ASTRH, tid, pr);
                __syncthreads();
            }

#pragma unroll
            for (int mi = 0; mi < 2; mi++) {
#pragma unroll
                for (int ni = 0; ni < 2; ni++) {
                    const int r = wm * 32 + mi * 16 + (lane >> 2);
                    const int c = wn * 16 + ni * 8 + 2 * (lane & 3);
                    const float b0 = g_bg[n0 + c], b1 = g_bg[n0 + c + 1];
                    Cs[r * CSTR + c]           = acc[mi][ni].x + b0;
                    Cs[r * CSTR + c + 1]       = acc[mi][ni].y + b1;
                    Cs[(r + 8) * CSTR + c]     = acc[mi][ni].z + b0;
                    Cs[(r + 8) * CSTR + c + 1] = acc[mi][ni].w + b1;
                }
            }
            __syncthreads();

#pragma unroll
            for (int s = 0; s < 4; s++) {
                const int it  = tid + s * NTH;
                const int u   = it & 15;
                const int row = it >> 4;
                const int jg  = (n0 >> 2) + u;
                const float4 cv = *(const float4*)(Cs + row * CSTR + 4 * u);
                const float rg = sigf(cv.x);
                const float zg = sigf(cv.y);
                const float nn = tanhf(cv.z + rg * cv.w);
                const float xn = (1.f - zg) * nn + zg * hp[s];
                const int oi = row * HH + jg;
                xo32[oi] = xn;
                xoh[oi]  = __float2half_rn(xn);
                so[oi]   = __float2half_rn(fmaxf(xn, 0.f));
            }

            bar_arrive(g_bar_gru);
            if (t < TSTEPS - 1) {
                wait_ge(g_bar_gru, 32u * (unsigned)t);
                if (t == 1) {   // swap to combined weights for t >= 2
                    for (int i = tid; i < 64 * 64; i += NTH) {
                        const int r = i >> 6, c = (i & 63) * 8;
                        *(uint4*)(Ws + r * WSTRH_G + c) =
                            *(const uint4*)(g_Wgh + (size_t)(n0 + r) * HH + c);
                    }
                    __syncthreads();
                }
            }
        }
        fc_worker(smh, fcb, out);

    } else if (bid < 64) {
        // ================= XG: Xg[t] = seq[t] @ Wih^T + bl, 128 cols =================
        __half* Ws = smh;                     // [128][WSTRH_G]
        __half* As = smh + 128 * WSTRH_G;     // [2][128][ASTRH]
        const int n0 = (bid - 32) * 128;

        for (int i = tid; i < 128 * 64; i += NTH) {
            const int r = i >> 6, c = (i & 63) * 8;
            *(uint4*)(Ws + r * WSTRH_G + c) = *(const uint4*)(g_Wihlh + (size_t)(n0 + r) * HH + c);
        }
        __syncthreads();

        for (int t = 1; t < TSTEPS; ++t) {
            wait_ge(g_bar_gru, 32u * (unsigned)t);
            const __half* Abh = g_seqh + (size_t)t * BB * HH;

            float4 acc[2][4];
#pragma unroll
            for (int mi = 0; mi < 2; mi++)
#pragma unroll
                for (int ni = 0; ni < 4; ni++) acc[mi][ni] = make_float4(0.f, 0.f, 0.f, 0.f);

            uint4 pr[2];
            a_load(Abh, HH, 0, tid, pr);
            a_store(As, tid, pr);
            __syncthreads();
            for (int kt = 0; kt < 8; ++kt) {
                const int  cur  = kt & 1;
                const bool more = (kt + 1 < 8);
                if (more) a_load(Abh, HH, (kt + 1) * PBK, tid, pr);
                do_kk4<4>(As + cur * BM * ASTRH, Ws, WSTRH_G, kt * PBK, lane, wm, wn, acc);
                if (more) a_store(As + ((kt + 1) & 1) * BM * ASTRH, tid, pr);
                __syncthreads();
            }

#pragma unroll
            for (int mi = 0; mi < 2; mi++) {
#pragma unroll
                for (int ni = 0; ni < 4; ni++) {
                    const int r   = wm * 32 + mi * 16 + (lane >> 2);
                    const int col = n0 + wn * 32 + ni * 8 + 2 * (lane & 3);
                    const float b0 = g_bl[col], b1 = g_bl[col + 1];
                    float* o0 = g_Xg + ((size_t)t * BB + r) * 4096 + col;
                    float* o1 = g_Xg + ((size_t)t * BB + r + 8) * 4096 + col;
                    *(float2*)o0 = make_float2(acc[mi][ni].x + b0, acc[mi][ni].y + b1);
                    *(float2*)o1 = make_float2(acc[mi][ni].z + b0, acc[mi][ni].w + b1);
                }
            }
            bar_arrive(g_bar_xg);
        }
        fc_worker(smh, fcb, out);

    } else if (bid < 128) {
        // ================= LSTM chain: 64 cols (16 units) =================
        __half* Ws = smh;                     // [64][WSTRH_L]
        __half* As = smh + 64 * WSTRH_L;      // [2][128][ASTRH]
        float*  Cs = (float*)As;              // staging, stride CSTR
        const int n0 = (bid - 64) * 64;

        for (int i = tid; i < 64 * 128; i += NTH) {
            const int r = i >> 7, c = (i & 127) * 8;
            *(uint4*)(Ws + r * WSTRH_L + c) = *(const uint4*)(g_Whhlh + (size_t)(n0 + r) * LL + c);
        }
        __syncthreads();

        for (int t = 0; t < TSTEPS; ++t) {
            if (t >= 1)
                wait_ge2(g_bar_xg, 32u * (unsigned)t, g_bar_lstm, 64u * (unsigned)t);

            const __half* Abh = g_hh + (size_t)(t & 1) * BB * LL;
            __half* hoh       = g_hh + (size_t)((t + 1) & 1) * BB * LL;

            // prefetch Xg[t] and c before the mainloop
            float4 xg[4];
            float  cc[4];
#pragma unroll
            for (int s = 0; s < 4; s++) {
                const int it  = tid + s * NTH;
                const int row = it >> 4;
                const int u   = it & 15;
                xg[s] = *(const float4*)(g_Xg + ((size_t)t * BB + row) * 4096 + n0 + 4 * u);
                cc[s] = g_c[row * LL + (n0 >> 2) + u];
            }

            float4 acc[2][2];
#pragma unroll
            for (int mi = 0; mi < 2; mi++)
#pragma unroll
                for (int ni = 0; ni < 2; ni++) acc[mi][ni] = make_float4(0.f, 0.f, 0.f, 0.f);

            if (t >= 1) {   // t == 0: h = 0 -> matmul contributes nothing
                uint4 pr[2];
                a_load(Abh, LL, 0, tid, pr);
                a_store(As, tid, pr);
                __syncthreads();
                for (int kt = 0; kt < 16; ++kt) {
                    const int  cur  = kt & 1;
                    const bool more = (kt + 1 < 16);
                    if (more) a_load(Abh, LL, (kt + 1) * PBK, tid, pr);
                    do_kk4<2>(As + cur * BM * ASTRH, Ws, WSTRH_L, kt * PBK, lane, wm, wn, acc);
                    if (more) a_store(As + ((kt + 1) & 1) * BM * ASTRH, tid, pr);
                    __syncthreads();
                }
            }

#pragma unroll
            for (int mi = 0; mi < 2; mi++) {
#pragma unroll
                for (int ni = 0; ni < 2; ni++) {
                    const int r = wm * 32 + mi * 16 + (lane >> 2);
                    const int c = wn * 16 + ni * 8 + 2 * (lane & 3);
                    Cs[r * CSTR + c]           = acc[mi][ni].x;
                    Cs[r * CSTR + c + 1]       = acc[mi][ni].y;
                    Cs[(r + 8) * CSTR + c]     = acc[mi][ni].z;
                    Cs[(r + 8) * CSTR + c + 1] = acc[mi][ni].w;
                }
            }
            __syncthreads();

#pragma unroll
            for (int s = 0; s < 4; s++) {
                const int it  = tid + s * NTH;
                const int u   = it & 15;
                const int row = it >> 4;
                const int jg  = (n0 >> 2) + u;
                const float4 cv = *(const float4*)(Cs + row * CSTR + 4 * u);
                const float ig = sigf(cv.x + xg[s].x);
                const float fg = sigf(cv.y + xg[s].y);
                const float gg = tanhf(cv.z + xg[s].z);
                const float og = sigf(cv.w + xg[s].w);
                const int ci = row * LL + jg;
                const float cn = fg * cc[s] + ig * gg;
                g_c[ci] = cn;
                const float hn = og * tanhf(cn);
                hoh[ci] = __float2half_rn(hn);
                g_hsh[((size_t)t * BB + row) * LL + jg] = __float2half_rn(hn);
            }

            bar_arrive(g_bar_lstm);
        }
        fc_worker(smh, fcb, out);

    } else {
        fc_worker(smh, fcb, out);
    }
}

// ---------------- prep kernels ----------------
__global__ void prep_gru(const float* __restrict__ Wih, const float* __restrict__ Whh,
                         const float* __restrict__ bih, const float* __restrict__ bhh) {
    const int idx = blockIdx.x * blockDim.x + threadIdx.x;
    if (idx < 2048 * 512) {
        const int row = idx >> 9, k = idx & 511;
        const int j = row >> 2, g = row & 3;
        float wg, w1;
        if (g == 0)      { wg = Wih[j * 512 + k] + Whh[j * 512 + k];                 w1 = Whh[j * 512 + k]; }
        else if (g == 1) { wg = Wih[(512 + j) * 512 + k] + Whh[(512 + j) * 512 + k]; w1 = Whh[(512 + j) * 512 + k]; }
        else if (g == 2) { wg = Wih[(1024 + j) * 512 + k];                           w1 = 0.f; }
        else             { wg = Whh[(1024 + j) * 512 + k];                           w1 = wg; }
        g_Wgh[idx]  = __float2half_rn(wg);
        g_Wg1h[idx] = __float2half_rn(w1);
    }
    if (idx < 2048) {
        const int j = idx >> 2, g = idx & 3;
        float b;
        if (g == 0)      b = bih[j] + bhh[j];
        else if (g == 1) b = bih[512 + j] + bhh[512 + j];
        else if (g == 2) b = bih[1024 + j];
        else             b = bhh[1024 + j];
        g_bg[idx] = b;
    }
}

__global__ void prep_lstm(const float* __restrict__ Wih, const float* __restrict__ Whh,
                          const float* __restrict__ bih, const float* __restrict__ bhh,
                          const float* __restrict__ fcW) {
    const int idx = blockIdx.x * blockDim.x + threadIdx.x;
    if (idx < 4096 * 1024) {
        const int row = idx >> 10, k = idx & 1023;
        const int j = row >> 2, p = row & 3;
        g_Whhlh[idx] = __float2half_rn(Whh[(size_t)(p * 1024 + j) * 1024 + k]);
    }
    if (idx < 4096 * 512) {
        const int row = idx >> 9, k = idx & 511;
        const int j = row >> 2, p = row & 3;
        g_Wihlh[idx] = __float2half_rn(Wih[(size_t)(p * 1024 + j) * 512 + k]);
    }
    if (idx < 1024 * 1024) {
        g_fcWh[idx] = __float2half_rn(fcW[idx]);
    }
    if (idx < 4096) {
        const int j = idx >> 2, p = idx & 3;
        g_bl[idx] = bih[p * 1024 + j] + bhh[p * 1024 + j];
    }
}

// zero states, half(z), Xg[0] = bl (seq[0] == 0), reset barriers
__global__ void prep_zero(const float* __restrict__ z) {
    const int idx = blockIdx.x * blockDim.x + threadIdx.x;
    if (idx < BB * LL) { g_hh[idx] = __float2half_rn(0.f); g_c[idx] = 0.f; }
    if (idx < BB * HH) { g_zh[idx] = __float2half_rn(z[idx]); }
    if (idx < BB * 4096) { g_Xg[idx] = g_bl[idx & 4095]; }
    if (idx == 0) { g_bar_gru[0] = 0u; g_bar_xg[0] = 0u; g_bar_lstm[0] = 0u; g_fc_cnt[0] = 0u; }
}

// ---------------- host launcher ----------------
extern "C" void kernel_launch(void* const* d_in, const int* in_sizes, int n_in,
                              void* d_out, int out_size) {
    const float* z    = (const float*)d_in[0];
    const float* gWih = (const float*)d_in[2];
    const float* gWhh = (const float*)d_in[3];
    const float* gbih = (const float*)d_in[4];
    const float* gbhh = (const float*)d_in[5];
    const float* lWih = (const float*)d_in[6];
    const float* lWhh = (const float*)d_in[7];
    const float* lbih = (const float*)d_in[8];
    const float* lbhh = (const float*)d_in[9];
    const float* fcW  = (const float*)d_in[10];
    const float* fcb  = (const float*)d_in[11];
    float* out = (float*)d_out;

    cudaFuncSetAttribute(fused_persist, cudaFuncAttributeMaxDynamicSharedMemorySize, SMEM_FUSED);

    prep_gru <<<(2048 * 512 + 255) / 256, 256>>>(gWih, gWhh, gbih, gbhh);
    prep_lstm<<<(4096 * 1024 + 255) / 256, 256>>>(lWih, lWhh, lbih, lbhh, fcW);
    prep_zero<<<(BB * 4096 + 255) / 256, 256>>>(z);

    // one fused persistent kernel: GRU | XG | LSTM | FC pipelined on disjoint
    // CTA sets (32 + 32 + 64 + 20 = 148), 512 threads/CTA (16 warps/SM)
    fused_persist<<<148, NTH, SMEM_FUSED>>>(z, fcb, out);
}